// round 1
// baseline (speedup 1.0000x reference)
#include <cuda_runtime.h>
#include <math.h>

#define BB   256
#define SS   512
#define DD   512
#define HH   512
#define FCC  64
#define OO   2
#define G4   2048   // 4*H

// Scratch (allocation-free contract: static __device__ globals)
__device__ float g_gx[(size_t)SS * BB * G4];   // [t*B + b][4H], biases folded in. 1 GiB
__device__ float g_h[2][BB * HH];
__device__ float g_c[2][BB * HH];

// ---------------------------------------------------------------------------
// Zero initial state (h0 = c0 = 0) — must run every call (deterministic).
// ---------------------------------------------------------------------------
__global__ void init_state()
{
    int i = blockIdx.x * blockDim.x + threadIdx.x;
    if (i < BB * HH) {
        g_h[0][i] = 0.0f;
        g_c[0][i] = 0.0f;
    }
}

// ---------------------------------------------------------------------------
// Precompute GX[t*B+b][gate*H + j] = x[b,t,:] @ Wg + bg[j]
// Tiled fp32 GEMM: BM=128, BN=64, BK=16, 256 threads, 8x4 microtile.
// Grid: (M/128 = 1024, N/64 = 8); one launch per gate.
// ---------------------------------------------------------------------------
__global__ void __launch_bounds__(256) gemm_xw(
    const float* __restrict__ x,     // [B,S,D]
    const float* __restrict__ W,     // [D,H]
    const float* __restrict__ bias,  // [H]
    int gate)
{
    __shared__ float As[16][128];
    __shared__ float Bs[16][64];

    const int m0  = blockIdx.x * 128;       // m = t*B + b
    const int n0  = blockIdx.y * 64;
    const int t   = m0 / BB;                 // 128 | 256 -> single t per tile
    const int b0  = m0 % BB;
    const int tid = threadIdx.x;
    const int tm  = tid & 15;                // m-group 0..15
    const int tn  = tid >> 4;                // n-group 0..15

    float acc[8][4];
    #pragma unroll
    for (int i = 0; i < 8; i++)
        #pragma unroll
        for (int j = 0; j < 4; j++) acc[i][j] = 0.0f;

    for (int k0 = 0; k0 < DD; k0 += 16) {
        // Load A tile (transpose to k-major in smem)
        #pragma unroll
        for (int r = 0; r < 2; r++) {
            int l  = tid + r * 256;          // 0..511
            int kg = (l & 3) * 4;
            int m  = l >> 2;                 // 0..127
            const float4 v = *(const float4*)(x + ((size_t)(b0 + m) * SS + t) * DD + k0 + kg);
            As[kg + 0][m] = v.x;
            As[kg + 1][m] = v.y;
            As[kg + 2][m] = v.z;
            As[kg + 3][m] = v.w;
        }
        // Load B tile (already k-major rows)
        {
            int ng = (tid & 15) * 4;
            int k  = tid >> 4;
            *(float4*)&Bs[k][ng] = *(const float4*)(W + (size_t)(k0 + k) * HH + n0 + ng);
        }
        __syncthreads();

        #pragma unroll
        for (int k = 0; k < 16; k++) {
            float a0[4], a1[4], bv[4];
            *(float4*)a0 = *(const float4*)&As[k][tm * 4];
            *(float4*)a1 = *(const float4*)&As[k][64 + tm * 4];
            *(float4*)bv = *(const float4*)&Bs[k][tn * 4];
            #pragma unroll
            for (int i = 0; i < 4; i++)
                #pragma unroll
                for (int j = 0; j < 4; j++) {
                    acc[i][j]     += a0[i] * bv[j];
                    acc[i + 4][j] += a1[i] * bv[j];
                }
        }
        __syncthreads();
    }

    // Epilogue: add bias, store to GX
    float bv[4];
    *(float4*)bv = *(const float4*)(bias + n0 + tn * 4);
    #pragma unroll
    for (int i = 0; i < 8; i++) {
        int m = (i < 4) ? (tm * 4 + i) : (64 + tm * 4 + (i - 4));
        float* out = g_gx + (size_t)(m0 + m) * G4 + (size_t)gate * HH + n0 + tn * 4;
        float4 v = make_float4(acc[i][0] + bv[0], acc[i][1] + bv[1],
                               acc[i][2] + bv[2], acc[i][3] + bv[3]);
        *(float4*)out = v;
    }
}

// ---------------------------------------------------------------------------
// One fused TLSTM timestep. Tile 32(b) x 32(h) per CTA, grid (8,16)=128 CTAs.
// Computes 5 GEMM tiles (4 gates from h_prev @ U*, decomp from c_prev @ Wd)
// over K=512, then applies the full elementwise update in the epilogue.
// Ping-pong state buffers: reads g_h/g_c[pp], writes [pp^1].
// ---------------------------------------------------------------------------
__global__ void __launch_bounds__(256) tlstm_step(
    const float* __restrict__ Ui,  const float* __restrict__ Uf,
    const float* __restrict__ Uog, const float* __restrict__ Uc,
    const float* __restrict__ Wd,  const float* __restrict__ bd,
    const float* __restrict__ timep, int t, int pp)
{
    __shared__ float hs[32][34];
    __shared__ float cs[32][34];
    __shared__ float Us[5][32][32];

    const float* h_in  = g_h[pp];
    const float* c_in  = g_c[pp];
    float*       h_out = g_h[pp ^ 1];
    float*       c_out = g_c[pp ^ 1];

    const int b0  = blockIdx.x * 32;
    const int j0  = blockIdx.y * 32;
    const int tid = threadIdx.x;
    const int tx  = tid & 15;    // h pair
    const int ty  = tid >> 4;    // b pair

    const float* Uptr[5] = {Ui, Uf, Uog, Uc, Wd};

    float acc[5][2][2] = {};

    for (int k0 = 0; k0 < HH; k0 += 32) {
        // Load h,c slabs transposed to k-major
        {
            int kg = (tid & 7) * 4;
            int b  = tid >> 3;               // 0..31
            float4 v = *(const float4*)(h_in + (size_t)(b0 + b) * HH + k0 + kg);
            hs[kg + 0][b] = v.x; hs[kg + 1][b] = v.y;
            hs[kg + 2][b] = v.z; hs[kg + 3][b] = v.w;
            float4 w = *(const float4*)(c_in + (size_t)(b0 + b) * HH + k0 + kg);
            cs[kg + 0][b] = w.x; cs[kg + 1][b] = w.y;
            cs[kg + 2][b] = w.z; cs[kg + 3][b] = w.w;
        }
        // Load 5 weight slabs (k-major already)
        #pragma unroll
        for (int g = 0; g < 5; g++) {
            int jg = (tid & 7) * 4;
            int k  = tid >> 3;               // 0..31
            *(float4*)&Us[g][k][jg] =
                *(const float4*)(Uptr[g] + (size_t)(k0 + k) * HH + j0 + jg);
        }
        __syncthreads();

        #pragma unroll 8
        for (int k = 0; k < 32; k++) {
            const float2 ah = *(const float2*)&hs[k][ty * 2];
            const float2 ac = *(const float2*)&cs[k][ty * 2];
            #pragma unroll
            for (int g = 0; g < 4; g++) {
                const float2 u = *(const float2*)&Us[g][k][tx * 2];
                acc[g][0][0] += ah.x * u.x;  acc[g][0][1] += ah.x * u.y;
                acc[g][1][0] += ah.y * u.x;  acc[g][1][1] += ah.y * u.y;
            }
            {
                const float2 u = *(const float2*)&Us[4][k][tx * 2];
                acc[4][0][0] += ac.x * u.x;  acc[4][0][1] += ac.x * u.y;
                acc[4][1][0] += ac.y * u.x;  acc[4][1][1] += ac.y * u.y;
            }
        }
        __syncthreads();
    }

    // Elementwise TLSTM update epilogue
    #pragma unroll
    for (int bb = 0; bb < 2; bb++) {
        const int b  = b0 + ty * 2 + bb;
        const float tv = timep[(size_t)b * SS + t];
        const float T  = 1.0f / logf(tv + 2.7183f);
        const float* gx = g_gx + ((size_t)t * BB + b) * G4;
        #pragma unroll
        for (int jj = 0; jj < 2; jj++) {
            const int j = j0 + tx * 2 + jj;
            const float cprev = c_in[(size_t)b * HH + j];
            const float cst   = tanhf(acc[4][bb][jj] + bd[j]);
            const float c1    = cprev - cst + T * cst;
            const float iv = 1.0f / (1.0f + expf(-(gx[0 * HH + j] + acc[0][bb][jj])));
            const float fv = 1.0f / (1.0f + expf(-(gx[1 * HH + j] + acc[1][bb][jj])));
            const float ov = 1.0f / (1.0f + expf(-(gx[2 * HH + j] + acc[2][bb][jj])));
            const float cn = tanhf(gx[3 * HH + j] + acc[3][bb][jj]);
            const float cnew = fv * c1 + iv * cn;
            c_out[(size_t)b * HH + j] = cnew;
            h_out[(size_t)b * HH + j] = ov * tanhf(cnew);
        }
    }
}

// ---------------------------------------------------------------------------
// Output head: out[b,:] = relu(h_last[b,:] @ Wo + bo) @ Ws + bs
// ---------------------------------------------------------------------------
__global__ void head_kernel(const float* __restrict__ Wo, const float* __restrict__ bo,
                            const float* __restrict__ Ws, const float* __restrict__ bs,
                            float* __restrict__ out, int pp_final)
{
    __shared__ float hrow[HH];
    __shared__ float fc[FCC];
    const int b = blockIdx.x;
    const float* h = g_h[pp_final] + (size_t)b * HH;
    for (int k = threadIdx.x; k < HH; k += blockDim.x) hrow[k] = h[k];
    __syncthreads();

    const int j = threadIdx.x;  // blockDim == FCC == 64
    float s = bo[j];
    for (int k = 0; k < HH; k++) s += hrow[k] * Wo[(size_t)k * FCC + j];
    fc[j] = fmaxf(s, 0.0f);
    __syncthreads();

    if (j < OO) {
        float r = bs[j];
        for (int q = 0; q < FCC; q++) r += fc[q] * Ws[(size_t)q * OO + j];
        out[(size_t)b * OO + j] = r;
    }
}

// ---------------------------------------------------------------------------
extern "C" void kernel_launch(void* const* d_in, const int* in_sizes, int n_in,
                              void* d_out, int out_size)
{
    const float* x   = (const float*)d_in[0];
    const float* tmv = (const float*)d_in[1];
    const float* Wi  = (const float*)d_in[2];
    const float* Ui  = (const float*)d_in[3];
    const float* bi  = (const float*)d_in[4];
    const float* Wf  = (const float*)d_in[5];
    const float* Uf  = (const float*)d_in[6];
    const float* bf  = (const float*)d_in[7];
    const float* Wog = (const float*)d_in[8];
    const float* Uog = (const float*)d_in[9];
    const float* bog = (const float*)d_in[10];
    const float* Wc  = (const float*)d_in[11];
    const float* Uc  = (const float*)d_in[12];
    const float* bc  = (const float*)d_in[13];
    const float* Wd  = (const float*)d_in[14];
    const float* bd  = (const float*)d_in[15];
    const float* Wo  = (const float*)d_in[16];
    const float* bo  = (const float*)d_in[17];
    const float* Ws  = (const float*)d_in[18];
    const float* bs  = (const float*)d_in[19];
    float* out = (float*)d_out;

    init_state<<<(BB * HH + 255) / 256, 256>>>();

    dim3 gg(1024, 8);
    gemm_xw<<<gg, 256>>>(x, Wi,  bi,  0);
    gemm_xw<<<gg, 256>>>(x, Wf,  bf,  1);
    gemm_xw<<<gg, 256>>>(x, Wog, bog, 2);
    gemm_xw<<<gg, 256>>>(x, Wc,  bc,  3);

    dim3 gs(8, 16);
    for (int t = 0; t < SS; t++)
        tlstm_step<<<gs, 256>>>(Ui, Uf, Uog, Uc, Wd, bd, tmv, t, t & 1);

    // step 511 reads buffer 1, writes buffer 0 -> final state in buffer 0
    head_kernel<<<256, 64>>>(Wo, bo, Ws, bs, out, 0);
}

// round 2
// speedup vs baseline: 1.9825x; 1.9825x over previous
#include <cuda_runtime.h>
#include <cuda_bf16.h>
#include <math.h>

#define BB   256
#define SS   512
#define DD   512
#define HH   512
#define FCC  64
#define OO   2
#define G4   2048          // 4*H
#define KE   1536          // tripled K (hi*hi, hi*lo, lo*hi)
#define NK   48            // KE / 32
#define N5   2560          // 5*H

// ---------------------------------------------------------------------------
// Static device scratch (allocation-free contract)
// ---------------------------------------------------------------------------
__device__ float         g_gx[(size_t)SS * BB * G4];        // [t*B+b][4H] preacts + bias
__device__ __nv_bfloat16 g_Axhi[(size_t)SS * BB * DD];      // A planes for precompute
__device__ __nv_bfloat16 g_Axlo[(size_t)SS * BB * DD];
__device__ __nv_bfloat16 g_Wstack[(size_t)KE * G4];         // [1536][2048]  (hi;lo;hi)
__device__ __nv_bfloat16 g_Ustack[(size_t)KE * N5];         // [1536][2560]  (hi;lo;hi)
__device__ float         g_bstack[G4];
__device__ float         g_h[2][BB * HH];
__device__ float         g_c[2][BB * HH];
__device__ __nv_bfloat16 g_hhi[2][BB * HH];
__device__ __nv_bfloat16 g_hlo[2][BB * HH];
__device__ __nv_bfloat16 g_chi[2][BB * HH];
__device__ __nv_bfloat16 g_clo[2][BB * HH];

// ---------------------------------------------------------------------------
// PTX helpers
// ---------------------------------------------------------------------------
__device__ __forceinline__ unsigned smem_u32(const void* p)
{
    return (unsigned)__cvta_generic_to_shared(p);
}

#define CP_ASYNC16(dst_u32, src_ptr) \
    asm volatile("cp.async.cg.shared.global [%0],[%1],16;" :: "r"(dst_u32), "l"(src_ptr))
#define CP_COMMIT   asm volatile("cp.async.commit_group;")
#define CP_WAIT1    asm volatile("cp.async.wait_group 1;")
#define CP_WAIT0    asm volatile("cp.async.wait_group 0;")

#define LDSM_X4(r, addr) \
    asm volatile("ldmatrix.sync.aligned.m8n8.x4.shared.b16 {%0,%1,%2,%3},[%4];" \
                 : "=r"((r)[0]), "=r"((r)[1]), "=r"((r)[2]), "=r"((r)[3]) : "r"(addr))
#define LDSM_X4_T(r, addr) \
    asm volatile("ldmatrix.sync.aligned.m8n8.x4.trans.shared.b16 {%0,%1,%2,%3},[%4];" \
                 : "=r"((r)[0]), "=r"((r)[1]), "=r"((r)[2]), "=r"((r)[3]) : "r"(addr))

#define MMA_BF16(d, a, b) \
    asm volatile("mma.sync.aligned.m16n8k16.row.col.f32.bf16.bf16.f32 " \
                 "{%0,%1,%2,%3},{%4,%5,%6,%7},{%8,%9},{%0,%1,%2,%3};" \
                 : "+f"((d)[0]), "+f"((d)[1]), "+f"((d)[2]), "+f"((d)[3]) \
                 : "r"((a)[0]), "r"((a)[1]), "r"((a)[2]), "r"((a)[3]), \
                   "r"((b)[0]), "r"((b)[1]))

__device__ __forceinline__ float sigf(float x) { return 1.0f / (1.0f + expf(-x)); }

// ---------------------------------------------------------------------------
// Prep kernels
// ---------------------------------------------------------------------------
__global__ void init_state()
{
    int i = blockIdx.x * blockDim.x + threadIdx.x;
    if (i < BB * HH) {
        g_h[0][i] = 0.0f;  g_c[0][i] = 0.0f;
        __nv_bfloat16 z = __float2bfloat16(0.0f);
        g_hhi[0][i] = z; g_hlo[0][i] = z; g_chi[0][i] = z; g_clo[0][i] = z;
    }
}

// x[b][t][k] -> Axhi/Axlo[(t*B+b)][k]
__global__ void convert_x(const float* __restrict__ x)
{
    size_t idx = (size_t)blockIdx.x * blockDim.x + threadIdx.x;
    if (idx >= (size_t)SS * BB * DD) return;
    int k = (int)(idx & (DD - 1));
    int m = (int)(idx >> 9);
    int b = m & (BB - 1);
    int t = m >> 8;
    float v = x[((size_t)b * SS + t) * DD + k];
    __nv_bfloat16 hi = __float2bfloat16(v);
    g_Axhi[idx] = hi;
    g_Axlo[idx] = __float2bfloat16(v - __bfloat162float(hi));
}

// Wstack[1536][2048] from Wi,Wf,Wog,Wc ([512][512] each)
__global__ void prep_wstack(const float* __restrict__ Wi, const float* __restrict__ Wf,
                            const float* __restrict__ Wog, const float* __restrict__ Wc)
{
    size_t idx = (size_t)blockIdx.x * blockDim.x + threadIdx.x;
    if (idx >= (size_t)KE * G4) return;
    int n = (int)(idx % G4);
    int k = (int)(idx / G4);
    int g = n >> 9;
    int j = n & (HH - 1);
    const float* src = (g == 0) ? Wi : (g == 1) ? Wf : (g == 2) ? Wog : Wc;
    float v = src[(size_t)(k & (HH - 1)) * HH + j];
    __nv_bfloat16 hi = __float2bfloat16(v);
    __nv_bfloat16 out;
    if (k < 512)       out = hi;
    else if (k < 1024) out = __float2bfloat16(v - __bfloat162float(hi));
    else               out = hi;
    g_Wstack[idx] = out;
}

// Ustack[1536][2560] from Ui,Uf,Uog,Uc,Wd
__global__ void prep_ustack(const float* __restrict__ Ui, const float* __restrict__ Uf,
                            const float* __restrict__ Uog, const float* __restrict__ Uc,
                            const float* __restrict__ Wd)
{
    size_t idx = (size_t)blockIdx.x * blockDim.x + threadIdx.x;
    if (idx >= (size_t)KE * N5) return;
    int n = (int)(idx % N5);
    int k = (int)(idx / N5);
    int g = n >> 9;
    int j = n & (HH - 1);
    const float* src = (g == 0) ? Ui : (g == 1) ? Uf : (g == 2) ? Uog : (g == 3) ? Uc : Wd;
    float v = src[(size_t)(k & (HH - 1)) * HH + j];
    __nv_bfloat16 hi = __float2bfloat16(v);
    __nv_bfloat16 out;
    if (k < 512)       out = hi;
    else if (k < 1024) out = __float2bfloat16(v - __bfloat162float(hi));
    else               out = hi;
    g_Ustack[idx] = out;
}

__global__ void prep_bias(const float* __restrict__ bi, const float* __restrict__ bf,
                          const float* __restrict__ bog, const float* __restrict__ bc)
{
    int n = blockIdx.x * blockDim.x + threadIdx.x;
    if (n >= G4) return;
    int g = n >> 9, j = n & (HH - 1);
    const float* src = (g == 0) ? bi : (g == 1) ? bf : (g == 2) ? bog : bc;
    g_bstack[n] = src[j];
}

// ---------------------------------------------------------------------------
// Precompute GEMM: g_gx[m][n] = Astack[m][:] @ Wstack[:][n] + bstack[n]
// M=131072, N=2048, K=1536.  CTA tile 128x64, 8 warps (4m x 2n), warp 32x32.
// ---------------------------------------------------------------------------
__global__ void __launch_bounds__(256) gemm_pre()
{
    __shared__ __nv_bfloat16 As[2][128][40];
    __shared__ __nv_bfloat16 Bs[2][32][72];

    const int m0 = blockIdx.x * 128;
    const int n0 = blockIdx.y * 64;
    const int tid = threadIdx.x;
    const int warp = tid >> 5, lane = tid & 31;
    const int wm = warp & 3, wn = warp >> 2;

    // ldmatrix lane mapping
    const int lrow = (lane & 7) + ((lane >> 3) & 1) * 8;
    const int lcol = (lane >> 4) * 8;

    float acc[2][4][4];
    #pragma unroll
    for (int a = 0; a < 2; a++)
        #pragma unroll
        for (int b = 0; b < 4; b++)
            #pragma unroll
            for (int c = 0; c < 4; c++) acc[a][b][c] = 0.0f;

    // load coords
    const int ar0 = (tid)       >> 2, ac0 = (tid & 3) * 8;        // A chunk 0
    const int ar1 = (tid + 256) >> 2;                              // A chunk 1 (same col)
    const int br  = tid >> 3,        bc = (tid & 7) * 8;          // B chunk

    auto load_stage = [&](int st, int kk) {
        const __nv_bfloat16* aBase = (kk < 1024) ? g_Axhi : g_Axlo;
        int acol = (kk & 511);
        CP_ASYNC16(smem_u32(&As[st][ar0][ac0]),
                   aBase + (size_t)(m0 + ar0) * DD + acol + ac0);
        CP_ASYNC16(smem_u32(&As[st][ar1][ac0]),
                   aBase + (size_t)(m0 + ar1) * DD + acol + ac0);
        CP_ASYNC16(smem_u32(&Bs[st][br][bc]),
                   g_Wstack + (size_t)(kk + br) * G4 + n0 + bc);
    };

    load_stage(0, 0);
    CP_COMMIT;

    for (int it = 0; it < NK; ++it) {
        if (it + 1 < NK) { load_stage((it + 1) & 1, (it + 1) * 32); CP_COMMIT; CP_WAIT1; }
        else            { CP_WAIT0; }
        __syncthreads();

        const int st = it & 1;
        #pragma unroll
        for (int kh = 0; kh < 2; kh++) {        // two k16 chunks
            const int kb = kh * 16;
            unsigned afr[2][4], bfr[2][4];
            #pragma unroll
            for (int mt = 0; mt < 2; mt++)
                LDSM_X4(afr[mt], smem_u32(&As[st][wm * 32 + mt * 16 + lrow][kb + lcol]));
            #pragma unroll
            for (int nt = 0; nt < 2; nt++)
                LDSM_X4_T(bfr[nt], smem_u32(&Bs[st][kb + lrow][wn * 32 + nt * 16 + lcol]));
            #pragma unroll
            for (int mt = 0; mt < 2; mt++)
                #pragma unroll
                for (int nx = 0; nx < 4; nx++)
                    MMA_BF16(acc[mt][nx], afr[mt], &bfr[nx >> 1][(nx & 1) * 2]);
        }
        __syncthreads();
    }

    // epilogue: + bias, fp32 store
    const int qrow = lane >> 2, qcol = (lane & 3) * 2;
    #pragma unroll
    for (int mt = 0; mt < 2; mt++) {
        #pragma unroll
        for (int rr = 0; rr < 2; rr++) {
            int m = m0 + wm * 32 + mt * 16 + qrow + rr * 8;
            #pragma unroll
            for (int nx = 0; nx < 4; nx++) {
                int n = n0 + wn * 32 + nx * 8 + qcol;
                float2 bv = *(const float2*)&g_bstack[n];
                float2 v = make_float2(acc[mt][nx][rr * 2 + 0] + bv.x,
                                       acc[mt][nx][rr * 2 + 1] + bv.y);
                *(float2*)&g_gx[(size_t)m * G4 + n] = v;
            }
        }
    }
}

// ---------------------------------------------------------------------------
// Fused TLSTM step. CTA tile: 32 batch x 32 hidden, computes all 5 gate tiles
// (4 gates from h hi/lo planes, decomp from c hi/lo planes) over KE=1536,
// then does the full elementwise update in the epilogue.
// Grid (8, 16) = 128 CTAs, 128 threads (4 warps, warp tile 16x16).
// ---------------------------------------------------------------------------
__global__ void __launch_bounds__(128) tlstm_step_mma(
    const float* __restrict__ timep, const float* __restrict__ bd, int t, int pp)
{
    __shared__ __nv_bfloat16 hs[2][32][40];
    __shared__ __nv_bfloat16 cs[2][32][40];
    __shared__ __nv_bfloat16 Bsh[2][5][32][40];

    const int m0 = blockIdx.x * 32;
    const int j0 = blockIdx.y * 32;
    const int tid = threadIdx.x;
    const int warp = tid >> 5, lane = tid & 31;
    const int wm = warp & 1, wj = warp >> 1;

    const __nv_bfloat16* hhi = g_hhi[pp];
    const __nv_bfloat16* hlo = g_hlo[pp];
    const __nv_bfloat16* chi = g_chi[pp];
    const __nv_bfloat16* clo = g_clo[pp];

    const int lrow = (lane & 7) + ((lane >> 3) & 1) * 8;
    const int lcol = (lane >> 4) * 8;

    float accG[4][2][4];   // gates (A = h)
    float accD[2][4];      // decomp (A = c)
    #pragma unroll
    for (int g = 0; g < 4; g++)
        #pragma unroll
        for (int n = 0; n < 2; n++)
            #pragma unroll
            for (int c = 0; c < 4; c++) accG[g][n][c] = 0.0f;
    #pragma unroll
    for (int n = 0; n < 2; n++)
        #pragma unroll
        for (int c = 0; c < 4; c++) accD[n][c] = 0.0f;

    const int arow = tid >> 2, acol = (tid & 3) * 8;   // one 16B chunk each for hs/cs/Bsh[g]

    auto load_stage = [&](int st, int kk) {
        const __nv_bfloat16* hB = (kk < 1024) ? hhi : hlo;
        const __nv_bfloat16* cB = (kk < 1024) ? chi : clo;
        int pcol = (kk & 511) + acol;
        CP_ASYNC16(smem_u32(&hs[st][arow][acol]), hB + (size_t)(m0 + arow) * HH + pcol);
        CP_ASYNC16(smem_u32(&cs[st][arow][acol]), cB + (size_t)(m0 + arow) * HH + pcol);
        #pragma unroll
        for (int g = 0; g < 5; g++)
            CP_ASYNC16(smem_u32(&Bsh[st][g][arow][acol]),
                       g_Ustack + (size_t)(kk + arow) * N5 + g * HH + j0 + acol);
    };

    load_stage(0, 0);
    CP_COMMIT;

    for (int it = 0; it < NK; ++it) {
        if (it + 1 < NK) { load_stage((it + 1) & 1, (it + 1) * 32); CP_COMMIT; CP_WAIT1; }
        else            { CP_WAIT0; }
        __syncthreads();

        const int st = it & 1;
        #pragma unroll
        for (int kh = 0; kh < 2; kh++) {
            const int kb = kh * 16;
            unsigned ah[4], ac[4], bfr[4];
            LDSM_X4(ah, smem_u32(&hs[st][wm * 16 + lrow][kb + lcol]));
            LDSM_X4(ac, smem_u32(&cs[st][wm * 16 + lrow][kb + lcol]));
            #pragma unroll
            for (int g = 0; g < 4; g++) {
                LDSM_X4_T(bfr, smem_u32(&Bsh[st][g][kb + lrow][wj * 16 + lcol]));
                MMA_BF16(accG[g][0], ah, &bfr[0]);
                MMA_BF16(accG[g][1], ah, &bfr[2]);
            }
            LDSM_X4_T(bfr, smem_u32(&Bsh[st][4][kb + lrow][wj * 16 + lcol]));
            MMA_BF16(accD[0], ac, &bfr[0]);
            MMA_BF16(accD[1], ac, &bfr[2]);
        }
        __syncthreads();
    }

    // ---------------- elementwise TLSTM update epilogue ----------------
    const float* c_in  = g_c[pp];
    float*       h_out = g_h[pp ^ 1];
    float*       c_out = g_c[pp ^ 1];
    __nv_bfloat16* hhi_o = g_hhi[pp ^ 1];
    __nv_bfloat16* hlo_o = g_hlo[pp ^ 1];
    __nv_bfloat16* chi_o = g_chi[pp ^ 1];
    __nv_bfloat16* clo_o = g_clo[pp ^ 1];

    const int qrow = lane >> 2, qcol = (lane & 3) * 2;

    #pragma unroll
    for (int rr = 0; rr < 2; rr++) {
        const int m  = m0 + wm * 16 + qrow + rr * 8;
        const float tv = timep[(size_t)m * SS + t];
        const float Tf = 1.0f / logf(tv + 2.7183f);
        const float* gxrow = g_gx + ((size_t)t * BB + m) * G4;
        #pragma unroll
        for (int n8 = 0; n8 < 2; n8++) {
            const int j = j0 + wj * 16 + n8 * 8 + qcol;
            const float2 gxi = *(const float2*)&gxrow[0 * HH + j];
            const float2 gxf = *(const float2*)&gxrow[1 * HH + j];
            const float2 gxo = *(const float2*)&gxrow[2 * HH + j];
            const float2 gxc = *(const float2*)&gxrow[3 * HH + j];
            const float2 cp  = *(const float2*)&c_in[(size_t)m * HH + j];
            const float2 bdv = *(const float2*)&bd[j];

            float d0 = accD[n8][rr * 2 + 0], d1 = accD[n8][rr * 2 + 1];
            float cst0 = tanhf(d0 + bdv.x), cst1 = tanhf(d1 + bdv.y);
            float c10 = cp.x - cst0 + Tf * cst0;
            float c11 = cp.y - cst1 + Tf * cst1;

            float i0 = sigf(accG[0][n8][rr * 2 + 0] + gxi.x);
            float i1 = sigf(accG[0][n8][rr * 2 + 1] + gxi.y);
            float f0 = sigf(accG[1][n8][rr * 2 + 0] + gxf.x);
            float f1 = sigf(accG[1][n8][rr * 2 + 1] + gxf.y);
            float o0 = sigf(accG[2][n8][rr * 2 + 0] + gxo.x);
            float o1 = sigf(accG[2][n8][rr * 2 + 1] + gxo.y);
            float n0v = tanhf(accG[3][n8][rr * 2 + 0] + gxc.x);
            float n1v = tanhf(accG[3][n8][rr * 2 + 1] + gxc.y);

            float cn0 = f0 * c10 + i0 * n0v;
            float cn1 = f1 * c11 + i1 * n1v;
            float hn0 = o0 * tanhf(cn0);
            float hn1 = o1 * tanhf(cn1);

            size_t off = (size_t)m * HH + j;
            *(float2*)&c_out[off] = make_float2(cn0, cn1);
            *(float2*)&h_out[off] = make_float2(hn0, hn1);

            __nv_bfloat16 ch0 = __float2bfloat16(cn0), ch1 = __float2bfloat16(cn1);
            __nv_bfloat16 hh0 = __float2bfloat16(hn0), hh1 = __float2bfloat16(hn1);
            *(__nv_bfloat162*)&chi_o[off] = __nv_bfloat162(ch0, ch1);
            *(__nv_bfloat162*)&clo_o[off] = __nv_bfloat162(
                __float2bfloat16(cn0 - __bfloat162float(ch0)),
                __float2bfloat16(cn1 - __bfloat162float(ch1)));
            *(__nv_bfloat162*)&hhi_o[off] = __nv_bfloat162(hh0, hh1);
            *(__nv_bfloat162*)&hlo_o[off] = __nv_bfloat162(
                __float2bfloat16(hn0 - __bfloat162float(hh0)),
                __float2bfloat16(hn1 - __bfloat162float(hh1)));
        }
    }
}

// ---------------------------------------------------------------------------
// Output head: out[b,:] = relu(h_last[b,:] @ Wo + bo) @ Ws + bs
// ---------------------------------------------------------------------------
__global__ void head_kernel(const float* __restrict__ Wo, const float* __restrict__ bo,
                            const float* __restrict__ Ws, const float* __restrict__ bs,
                            float* __restrict__ out)
{
    __shared__ float hrow[HH];
    __shared__ float fc[FCC];
    const int b = blockIdx.x;
    const float* h = g_h[0] + (size_t)b * HH;
    for (int k = threadIdx.x; k < HH; k += blockDim.x) hrow[k] = h[k];
    __syncthreads();

    const int j = threadIdx.x;  // blockDim == FCC == 64
    float s = bo[j];
    for (int k = 0; k < HH; k++) s += hrow[k] * Wo[(size_t)k * FCC + j];
    fc[j] = fmaxf(s, 0.0f);
    __syncthreads();

    if (j < OO) {
        float r = bs[j];
        for (int q = 0; q < FCC; q++) r += fc[q] * Ws[(size_t)q * OO + j];
        out[(size_t)b * OO + j] = r;
    }
}

// ---------------------------------------------------------------------------
extern "C" void kernel_launch(void* const* d_in, const int* in_sizes, int n_in,
                              void* d_out, int out_size)
{
    const float* x   = (const float*)d_in[0];
    const float* tmv = (const float*)d_in[1];
    const float* Wi  = (const float*)d_in[2];
    const float* Ui  = (const float*)d_in[3];
    const float* bi  = (const float*)d_in[4];
    const float* Wf  = (const float*)d_in[5];
    const float* Uf  = (const float*)d_in[6];
    const float* bf  = (const float*)d_in[7];
    const float* Wog = (const float*)d_in[8];
    const float* Uog = (const float*)d_in[9];
    const float* bog = (const float*)d_in[10];
    const float* Wc  = (const float*)d_in[11];
    const float* Uc  = (const float*)d_in[12];
    const float* bc  = (const float*)d_in[13];
    const float* Wd  = (const float*)d_in[14];
    const float* bd  = (const float*)d_in[15];
    const float* Wo  = (const float*)d_in[16];
    const float* bo  = (const float*)d_in[17];
    const float* Ws  = (const float*)d_in[18];
    const float* bs  = (const float*)d_in[19];
    float* out = (float*)d_out;

    init_state<<<(BB * HH + 255) / 256, 256>>>();

    {   size_t n = (size_t)SS * BB * DD;
        convert_x<<<(unsigned)((n + 255) / 256), 256>>>(x); }
    {   size_t n = (size_t)KE * G4;
        prep_wstack<<<(unsigned)((n + 255) / 256), 256>>>(Wi, Wf, Wog, Wc); }
    {   size_t n = (size_t)KE * N5;
        prep_ustack<<<(unsigned)((n + 255) / 256), 256>>>(Ui, Uf, Uog, Uc, Wd); }
    prep_bias<<<(G4 + 255) / 256, 256>>>(bi, bf, bog, bc);

    dim3 gg(1024, 32);
    gemm_pre<<<gg, 256>>>();

    dim3 gs(8, 16);
    for (int t = 0; t < SS; t++)
        tlstm_step_mma<<<gs, 128>>>(tmv, bd, t, t & 1);

    // step 511 reads buffer 1, writes buffer 0 -> final state in buffer 0
    head_kernel<<<BB, FCC>>>(Wo, bo, Ws, bs, out);
}

// round 3
// speedup vs baseline: 1.9834x; 1.0005x over previous
#include <cuda_runtime.h>
#include <cuda_bf16.h>
#include <math.h>

#define BB   256
#define SS   512
#define DD   512
#define HH   512
#define FCC  64
#define OO   2
#define G4   2048          // 4*H
#define KE   1536          // tripled K (hi*hi, hi*lo, lo*hi)
#define NK   48            // KE / 32
#define N5   2560          // 5*H

// ---------------------------------------------------------------------------
// Static device scratch (allocation-free contract)
// ---------------------------------------------------------------------------
__device__ float         g_gx[(size_t)SS * BB * G4];        // [t*B+b][4H] preacts + bias
__device__ __nv_bfloat16 g_Axhi[(size_t)SS * BB * DD];      // A planes for precompute
__device__ __nv_bfloat16 g_Axlo[(size_t)SS * BB * DD];
__device__ __nv_bfloat16 g_Wstack[(size_t)KE * G4];         // [1536][2048]  (hi;lo;hi)
__device__ __nv_bfloat16 g_Ustack[(size_t)KE * N5];         // [1536][2560]  (hi;lo;hi)
__device__ float         g_bstack[G4];
__device__ float         g_h[2][BB * HH];
__device__ float         g_c[2][BB * HH];
__device__ __nv_bfloat16 g_hhi[2][BB * HH];
__device__ __nv_bfloat16 g_hlo[2][BB * HH];
__device__ __nv_bfloat16 g_chi[2][BB * HH];
__device__ __nv_bfloat16 g_clo[2][BB * HH];

// ---------------------------------------------------------------------------
// PTX helpers
// ---------------------------------------------------------------------------
__device__ __forceinline__ unsigned smem_u32(const void* p)
{
    return (unsigned)__cvta_generic_to_shared(p);
}

#define CP_ASYNC16(dst_u32, src_ptr) \
    asm volatile("cp.async.cg.shared.global [%0],[%1],16;" :: "r"(dst_u32), "l"(src_ptr))
#define CP_COMMIT   asm volatile("cp.async.commit_group;")
#define CP_WAIT1    asm volatile("cp.async.wait_group 1;")
#define CP_WAIT0    asm volatile("cp.async.wait_group 0;")

#define LDSM_X4(r, addr) \
    asm volatile("ldmatrix.sync.aligned.m8n8.x4.shared.b16 {%0,%1,%2,%3},[%4];" \
                 : "=r"((r)[0]), "=r"((r)[1]), "=r"((r)[2]), "=r"((r)[3]) : "r"(addr))
#define LDSM_X4_T(r, addr) \
    asm volatile("ldmatrix.sync.aligned.m8n8.x4.trans.shared.b16 {%0,%1,%2,%3},[%4];" \
                 : "=r"((r)[0]), "=r"((r)[1]), "=r"((r)[2]), "=r"((r)[3]) : "r"(addr))

#define MMA_BF16(d, a, b) \
    asm volatile("mma.sync.aligned.m16n8k16.row.col.f32.bf16.bf16.f32 " \
                 "{%0,%1,%2,%3},{%4,%5,%6,%7},{%8,%9},{%0,%1,%2,%3};" \
                 : "+f"((d)[0]), "+f"((d)[1]), "+f"((d)[2]), "+f"((d)[3]) \
                 : "r"((a)[0]), "r"((a)[1]), "r"((a)[2]), "r"((a)[3]), \
                   "r"((b)[0]), "r"((b)[1]))

__device__ __forceinline__ float sigf(float x) { return 1.0f / (1.0f + expf(-x)); }

// ---------------------------------------------------------------------------
// Prep kernels
// ---------------------------------------------------------------------------
__global__ void init_state()
{
    int i = blockIdx.x * blockDim.x + threadIdx.x;
    if (i < BB * HH) {
        g_h[0][i] = 0.0f;  g_c[0][i] = 0.0f;
        __nv_bfloat16 z = __float2bfloat16(0.0f);
        g_hhi[0][i] = z; g_hlo[0][i] = z; g_chi[0][i] = z; g_clo[0][i] = z;
    }
}

// x[b][t][k] -> Axhi/Axlo[(t*B+b)][k]
__global__ void convert_x(const float* __restrict__ x)
{
    size_t idx = (size_t)blockIdx.x * blockDim.x + threadIdx.x;
    if (idx >= (size_t)SS * BB * DD) return;
    int k = (int)(idx & (DD - 1));
    int m = (int)(idx >> 9);
    int b = m & (BB - 1);
    int t = m >> 8;
    float v = x[((size_t)b * SS + t) * DD + k];
    __nv_bfloat16 hi = __float2bfloat16(v);
    g_Axhi[idx] = hi;
    g_Axlo[idx] = __float2bfloat16(v - __bfloat162float(hi));
}

// Wstack[1536][2048] from Wi,Wf,Wog,Wc ([512][512] each)
__global__ void prep_wstack(const float* __restrict__ Wi, const float* __restrict__ Wf,
                            const float* __restrict__ Wog, const float* __restrict__ Wc)
{
    size_t idx = (size_t)blockIdx.x * blockDim.x + threadIdx.x;
    if (idx >= (size_t)KE * G4) return;
    int n = (int)(idx % G4);
    int k = (int)(idx / G4);
    int g = n >> 9;
    int j = n & (HH - 1);
    const float* src = (g == 0) ? Wi : (g == 1) ? Wf : (g == 2) ? Wog : Wc;
    float v = src[(size_t)(k & (HH - 1)) * HH + j];
    __nv_bfloat16 hi = __float2bfloat16(v);
    __nv_bfloat16 out;
    if (k < 512)       out = hi;
    else if (k < 1024) out = __float2bfloat16(v - __bfloat162float(hi));
    else               out = hi;
    g_Wstack[idx] = out;
}

// Ustack[1536][2560] from Ui,Uf,Uog,Uc,Wd
__global__ void prep_ustack(const float* __restrict__ Ui, const float* __restrict__ Uf,
                            const float* __restrict__ Uog, const float* __restrict__ Uc,
                            const float* __restrict__ Wd)
{
    size_t idx = (size_t)blockIdx.x * blockDim.x + threadIdx.x;
    if (idx >= (size_t)KE * N5) return;
    int n = (int)(idx % N5);
    int k = (int)(idx / N5);
    int g = n >> 9;
    int j = n & (HH - 1);
    const float* src = (g == 0) ? Ui : (g == 1) ? Uf : (g == 2) ? Uog : (g == 3) ? Uc : Wd;
    float v = src[(size_t)(k & (HH - 1)) * HH + j];
    __nv_bfloat16 hi = __float2bfloat16(v);
    __nv_bfloat16 out;
    if (k < 512)       out = hi;
    else if (k < 1024) out = __float2bfloat16(v - __bfloat162float(hi));
    else               out = hi;
    g_Ustack[idx] = out;
}

__global__ void prep_bias(const float* __restrict__ bi, const float* __restrict__ bf,
                          const float* __restrict__ bog, const float* __restrict__ bc)
{
    int n = blockIdx.x * blockDim.x + threadIdx.x;
    if (n >= G4) return;
    int g = n >> 9, j = n & (HH - 1);
    const float* src = (g == 0) ? bi : (g == 1) ? bf : (g == 2) ? bog : bc;
    g_bstack[n] = src[j];
}

// ---------------------------------------------------------------------------
// Precompute GEMM: g_gx[m][n] = Astack[m][:] @ Wstack[:][n] + bstack[n]
// M=131072, N=2048, K=1536.  CTA tile 128x64, 8 warps (4m x 2n), warp 32x32.
// ---------------------------------------------------------------------------
__global__ void __launch_bounds__(256) gemm_pre()
{
    __shared__ __nv_bfloat16 As[2][128][40];
    __shared__ __nv_bfloat16 Bs[2][32][72];

    const int m0 = blockIdx.x * 128;
    const int n0 = blockIdx.y * 64;
    const int tid = threadIdx.x;
    const int warp = tid >> 5, lane = tid & 31;
    const int wm = warp & 3, wn = warp >> 2;

    // ldmatrix lane mapping
    const int lrow = (lane & 7) + ((lane >> 3) & 1) * 8;
    const int lcol = (lane >> 4) * 8;

    float acc[2][4][4];
    #pragma unroll
    for (int a = 0; a < 2; a++)
        #pragma unroll
        for (int b = 0; b < 4; b++)
            #pragma unroll
            for (int c = 0; c < 4; c++) acc[a][b][c] = 0.0f;

    // load coords
    const int ar0 = (tid)       >> 2, ac0 = (tid & 3) * 8;        // A chunk 0
    const int ar1 = (tid + 256) >> 2;                              // A chunk 1 (same col)
    const int br  = tid >> 3,        bc = (tid & 7) * 8;          // B chunk

    auto load_stage = [&](int st, int kk) {
        const __nv_bfloat16* aBase = (kk < 1024) ? g_Axhi : g_Axlo;
        int acol = (kk & 511);
        CP_ASYNC16(smem_u32(&As[st][ar0][ac0]),
                   aBase + (size_t)(m0 + ar0) * DD + acol + ac0);
        CP_ASYNC16(smem_u32(&As[st][ar1][ac0]),
                   aBase + (size_t)(m0 + ar1) * DD + acol + ac0);
        CP_ASYNC16(smem_u32(&Bs[st][br][bc]),
                   g_Wstack + (size_t)(kk + br) * G4 + n0 + bc);
    };

    load_stage(0, 0);
    CP_COMMIT;

    for (int it = 0; it < NK; ++it) {
        if (it + 1 < NK) { load_stage((it + 1) & 1, (it + 1) * 32); CP_COMMIT; CP_WAIT1; }
        else            { CP_WAIT0; }
        __syncthreads();

        const int st = it & 1;
        #pragma unroll
        for (int kh = 0; kh < 2; kh++) {        // two k16 chunks
            const int kb = kh * 16;
            unsigned afr[2][4], bfr[2][4];
            #pragma unroll
            for (int mt = 0; mt < 2; mt++)
                LDSM_X4(afr[mt], smem_u32(&As[st][wm * 32 + mt * 16 + lrow][kb + lcol]));
            #pragma unroll
            for (int nt = 0; nt < 2; nt++)
                LDSM_X4_T(bfr[nt], smem_u32(&Bs[st][kb + lrow][wn * 32 + nt * 16 + lcol]));
            #pragma unroll
            for (int mt = 0; mt < 2; mt++)
                #pragma unroll
                for (int nx = 0; nx < 4; nx++)
                    MMA_BF16(acc[mt][nx], afr[mt], &bfr[nx >> 1][(nx & 1) * 2]);
        }
        __syncthreads();
    }

    // epilogue: + bias, fp32 store
    const int qrow = lane >> 2, qcol = (lane & 3) * 2;
    #pragma unroll
    for (int mt = 0; mt < 2; mt++) {
        #pragma unroll
        for (int rr = 0; rr < 2; rr++) {
            int m = m0 + wm * 32 + mt * 16 + qrow + rr * 8;
            #pragma unroll
            for (int nx = 0; nx < 4; nx++) {
                int n = n0 + wn * 32 + nx * 8 + qcol;
                float2 bv = *(const float2*)&g_bstack[n];
                float2 v = make_float2(acc[mt][nx][rr * 2 + 0] + bv.x,
                                       acc[mt][nx][rr * 2 + 1] + bv.y);
                *(float2*)&g_gx[(size_t)m * G4 + n] = v;
            }
        }
    }
}

// ---------------------------------------------------------------------------
// Fused TLSTM step. CTA tile: 32 batch x 32 hidden, computes all 5 gate tiles
// (4 gates from h hi/lo planes, decomp from c hi/lo planes) over KE=1536,
// then does the full elementwise update in the epilogue.
// Grid (8, 16) = 128 CTAs, 128 threads (4 warps, warp tile 16x16).
// ---------------------------------------------------------------------------
__global__ void __launch_bounds__(128) tlstm_step_mma(
    const float* __restrict__ timep, const float* __restrict__ bd, int t, int pp)
{
    __shared__ __nv_bfloat16 hs[2][32][40];
    __shared__ __nv_bfloat16 cs[2][32][40];
    __shared__ __nv_bfloat16 Bsh[2][5][32][40];

    const int m0 = blockIdx.x * 32;
    const int j0 = blockIdx.y * 32;
    const int tid = threadIdx.x;
    const int warp = tid >> 5, lane = tid & 31;
    const int wm = warp & 1, wj = warp >> 1;

    const __nv_bfloat16* hhi = g_hhi[pp];
    const __nv_bfloat16* hlo = g_hlo[pp];
    const __nv_bfloat16* chi = g_chi[pp];
    const __nv_bfloat16* clo = g_clo[pp];

    const int lrow = (lane & 7) + ((lane >> 3) & 1) * 8;
    const int lcol = (lane >> 4) * 8;

    float accG[4][2][4];   // gates (A = h)
    float accD[2][4];      // decomp (A = c)
    #pragma unroll
    for (int g = 0; g < 4; g++)
        #pragma unroll
        for (int n = 0; n < 2; n++)
            #pragma unroll
            for (int c = 0; c < 4; c++) accG[g][n][c] = 0.0f;
    #pragma unroll
    for (int n = 0; n < 2; n++)
        #pragma unroll
        for (int c = 0; c < 4; c++) accD[n][c] = 0.0f;

    const int arow = tid >> 2, acol = (tid & 3) * 8;   // one 16B chunk each for hs/cs/Bsh[g]

    auto load_stage = [&](int st, int kk) {
        const __nv_bfloat16* hB = (kk < 1024) ? hhi : hlo;
        const __nv_bfloat16* cB = (kk < 1024) ? chi : clo;
        int pcol = (kk & 511) + acol;
        CP_ASYNC16(smem_u32(&hs[st][arow][acol]), hB + (size_t)(m0 + arow) * HH + pcol);
        CP_ASYNC16(smem_u32(&cs[st][arow][acol]), cB + (size_t)(m0 + arow) * HH + pcol);
        #pragma unroll
        for (int g = 0; g < 5; g++)
            CP_ASYNC16(smem_u32(&Bsh[st][g][arow][acol]),
                       g_Ustack + (size_t)(kk + arow) * N5 + g * HH + j0 + acol);
    };

    load_stage(0, 0);
    CP_COMMIT;

    for (int it = 0; it < NK; ++it) {
        if (it + 1 < NK) { load_stage((it + 1) & 1, (it + 1) * 32); CP_COMMIT; CP_WAIT1; }
        else            { CP_WAIT0; }
        __syncthreads();

        const int st = it & 1;
        #pragma unroll
        for (int kh = 0; kh < 2; kh++) {
            const int kb = kh * 16;
            unsigned ah[4], ac[4], bfr[4];
            LDSM_X4(ah, smem_u32(&hs[st][wm * 16 + lrow][kb + lcol]));
            LDSM_X4(ac, smem_u32(&cs[st][wm * 16 + lrow][kb + lcol]));
            #pragma unroll
            for (int g = 0; g < 4; g++) {
                LDSM_X4_T(bfr, smem_u32(&Bsh[st][g][kb + lrow][wj * 16 + lcol]));
                MMA_BF16(accG[g][0], ah, &bfr[0]);
                MMA_BF16(accG[g][1], ah, &bfr[2]);
            }
            LDSM_X4_T(bfr, smem_u32(&Bsh[st][4][kb + lrow][wj * 16 + lcol]));
            MMA_BF16(accD[0], ac, &bfr[0]);
            MMA_BF16(accD[1], ac, &bfr[2]);
        }
        __syncthreads();
    }

    // ---------------- elementwise TLSTM update epilogue ----------------
    const float* c_in  = g_c[pp];
    float*       h_out = g_h[pp ^ 1];
    float*       c_out = g_c[pp ^ 1];
    __nv_bfloat16* hhi_o = g_hhi[pp ^ 1];
    __nv_bfloat16* hlo_o = g_hlo[pp ^ 1];
    __nv_bfloat16* chi_o = g_chi[pp ^ 1];
    __nv_bfloat16* clo_o = g_clo[pp ^ 1];

    const int qrow = lane >> 2, qcol = (lane & 3) * 2;

    #pragma unroll
    for (int rr = 0; rr < 2; rr++) {
        const int m  = m0 + wm * 16 + qrow + rr * 8;
        const float tv = timep[(size_t)m * SS + t];
        const float Tf = 1.0f / logf(tv + 2.7183f);
        const float* gxrow = g_gx + ((size_t)t * BB + m) * G4;
        #pragma unroll
        for (int n8 = 0; n8 < 2; n8++) {
            const int j = j0 + wj * 16 + n8 * 8 + qcol;
            const float2 gxi = *(const float2*)&gxrow[0 * HH + j];
            const float2 gxf = *(const float2*)&gxrow[1 * HH + j];
            const float2 gxo = *(const float2*)&gxrow[2 * HH + j];
            const float2 gxc = *(const float2*)&gxrow[3 * HH + j];
            const float2 cp  = *(const float2*)&c_in[(size_t)m * HH + j];
            const float2 bdv = *(const float2*)&bd[j];

            float d0 = accD[n8][rr * 2 + 0], d1 = accD[n8][rr * 2 + 1];
            float cst0 = tanhf(d0 + bdv.x), cst1 = tanhf(d1 + bdv.y);
            float c10 = cp.x - cst0 + Tf * cst0;
            float c11 = cp.y - cst1 + Tf * cst1;

            float i0 = sigf(accG[0][n8][rr * 2 + 0] + gxi.x);
            float i1 = sigf(accG[0][n8][rr * 2 + 1] + gxi.y);
            float f0 = sigf(accG[1][n8][rr * 2 + 0] + gxf.x);
            float f1 = sigf(accG[1][n8][rr * 2 + 1] + gxf.y);
            float o0 = sigf(accG[2][n8][rr * 2 + 0] + gxo.x);
            float o1 = sigf(accG[2][n8][rr * 2 + 1] + gxo.y);
            float n0v = tanhf(accG[3][n8][rr * 2 + 0] + gxc.x);
            float n1v = tanhf(accG[3][n8][rr * 2 + 1] + gxc.y);

            float cn0 = f0 * c10 + i0 * n0v;
            float cn1 = f1 * c11 + i1 * n1v;
            float hn0 = o0 * tanhf(cn0);
            float hn1 = o1 * tanhf(cn1);

            size_t off = (size_t)m * HH + j;
            *(float2*)&c_out[off] = make_float2(cn0, cn1);
            *(float2*)&h_out[off] = make_float2(hn0, hn1);

            __nv_bfloat16 ch0 = __float2bfloat16(cn0), ch1 = __float2bfloat16(cn1);
            __nv_bfloat16 hh0 = __float2bfloat16(hn0), hh1 = __float2bfloat16(hn1);
            *(__nv_bfloat162*)&chi_o[off] = __nv_bfloat162(ch0, ch1);
            *(__nv_bfloat162*)&clo_o[off] = __nv_bfloat162(
                __float2bfloat16(cn0 - __bfloat162float(ch0)),
                __float2bfloat16(cn1 - __bfloat162float(ch1)));
            *(__nv_bfloat162*)&hhi_o[off] = __nv_bfloat162(hh0, hh1);
            *(__nv_bfloat162*)&hlo_o[off] = __nv_bfloat162(
                __float2bfloat16(hn0 - __bfloat162float(hh0)),
                __float2bfloat16(hn1 - __bfloat162float(hh1)));
        }
    }
}

// ---------------------------------------------------------------------------
// Output head: out[b,:] = relu(h_last[b,:] @ Wo + bo) @ Ws + bs
// ---------------------------------------------------------------------------
__global__ void head_kernel(const float* __restrict__ Wo, const float* __restrict__ bo,
                            const float* __restrict__ Ws, const float* __restrict__ bs,
                            float* __restrict__ out)
{
    __shared__ float hrow[HH];
    __shared__ float fc[FCC];
    const int b = blockIdx.x;
    const float* h = g_h[0] + (size_t)b * HH;
    for (int k = threadIdx.x; k < HH; k += blockDim.x) hrow[k] = h[k];
    __syncthreads();

    const int j = threadIdx.x;  // blockDim == FCC == 64
    float s = bo[j];
    for (int k = 0; k < HH; k++) s += hrow[k] * Wo[(size_t)k * FCC + j];
    fc[j] = fmaxf(s, 0.0f);
    __syncthreads();

    if (j < OO) {
        float r = bs[j];
        for (int q = 0; q < FCC; q++) r += fc[q] * Ws[(size_t)q * OO + j];
        out[(size_t)b * OO + j] = r;
    }
}

// ---------------------------------------------------------------------------
extern "C" void kernel_launch(void* const* d_in, const int* in_sizes, int n_in,
                              void* d_out, int out_size)
{
    const float* x   = (const float*)d_in[0];
    const float* tmv = (const float*)d_in[1];
    const float* Wi  = (const float*)d_in[2];
    const float* Ui  = (const float*)d_in[3];
    const float* bi  = (const float*)d_in[4];
    const float* Wf  = (const float*)d_in[5];
    const float* Uf  = (const float*)d_in[6];
    const float* bf  = (const float*)d_in[7];
    const float* Wog = (const float*)d_in[8];
    const float* Uog = (const float*)d_in[9];
    const float* bog = (const float*)d_in[10];
    const float* Wc  = (const float*)d_in[11];
    const float* Uc  = (const float*)d_in[12];
    const float* bc  = (const float*)d_in[13];
    const float* Wd  = (const float*)d_in[14];
    const float* bd  = (const float*)d_in[15];
    const float* Wo  = (const float*)d_in[16];
    const float* bo  = (const float*)d_in[17];
    const float* Ws  = (const float*)d_in[18];
    const float* bs  = (const float*)d_in[19];
    float* out = (float*)d_out;

    init_state<<<(BB * HH + 255) / 256, 256>>>();

    {   size_t n = (size_t)SS * BB * DD;
        convert_x<<<(unsigned)((n + 255) / 256), 256>>>(x); }
    {   size_t n = (size_t)KE * G4;
        prep_wstack<<<(unsigned)((n + 255) / 256), 256>>>(Wi, Wf, Wog, Wc); }
    {   size_t n = (size_t)KE * N5;
        prep_ustack<<<(unsigned)((n + 255) / 256), 256>>>(Ui, Uf, Uog, Uc, Wd); }
    prep_bias<<<(G4 + 255) / 256, 256>>>(bi, bf, bog, bc);

    dim3 gg(1024, 32);
    gemm_pre<<<gg, 256>>>();

    dim3 gs(8, 16);
    for (int t = 0; t < SS; t++)
        tlstm_step_mma<<<gs, 128>>>(tmv, bd, t, t & 1);

    // step 511 reads buffer 1, writes buffer 0 -> final state in buffer 0
    head_kernel<<<BB, FCC>>>(Wo, bo, Ws, bs, out);
}

// round 5
// speedup vs baseline: 2.0388x; 1.0279x over previous
#include <cuda_runtime.h>
#include <cuda_bf16.h>
#include <math.h>

#define BB   256
#define SS   512
#define DD   512
#define HH   512
#define FCC  64
#define OO   2
#define G4   2048          // 4*H
#define KE   1536          // tripled K (hi*hi, hi*lo, lo*hi)
#define NK   48            // KE / 32
#define N5   2560          // 5*H
#define NCTA 128           // scan grid (8 x 16)

// scan kernel dynamic smem layout (bf16 elements), row pad 40 (80B, 16B-aligned)
#define PAD      40
#define HS_OFF   0                      // [3][32][40]
#define CS_OFF   (3 * 32 * PAD)         // [3][32][40]
#define BS_OFF   (2 * 3 * 32 * PAD)     // [3][5][32][40]
#define SCAN_SMEM_BYTES ((2 * 3 * 32 * PAD + 3 * 5 * 32 * PAD) * 2)

// ---------------------------------------------------------------------------
// Static device scratch (allocation-free contract)
// ---------------------------------------------------------------------------
__device__ float         g_gx[(size_t)SS * BB * G4];        // [t*B+b][4H] preacts + bias
__device__ __nv_bfloat16 g_Axhi[(size_t)SS * BB * DD];      // A planes for precompute
__device__ __nv_bfloat16 g_Axlo[(size_t)SS * BB * DD];
__device__ __nv_bfloat16 g_Wstack[(size_t)KE * G4];         // [1536][2048]  (hi;lo;hi)
__device__ __nv_bfloat16 g_Ustack[(size_t)KE * N5];         // [1536][2560]  (hi;lo;hi)
__device__ float         g_bstack[G4];
__device__ float         g_h[2][BB * HH];
__device__ float         g_c[2][BB * HH];
__device__ __nv_bfloat16 g_hhi[2][BB * HH];
__device__ __nv_bfloat16 g_hlo[2][BB * HH];
__device__ __nv_bfloat16 g_chi[2][BB * HH];
__device__ __nv_bfloat16 g_clo[2][BB * HH];
__device__ unsigned      g_count;                            // grid barrier counter

// ---------------------------------------------------------------------------
// PTX helpers
// ---------------------------------------------------------------------------
__device__ __forceinline__ unsigned smem_u32(const void* p)
{
    return (unsigned)__cvta_generic_to_shared(p);
}

#define CP_ASYNC16(dst_u32, src_ptr) \
    asm volatile("cp.async.cg.shared.global [%0],[%1],16;" :: "r"(dst_u32), "l"(src_ptr))
#define CP_COMMIT   asm volatile("cp.async.commit_group;")
#define CP_WAIT1    asm volatile("cp.async.wait_group 1;")
#define CP_WAIT0    asm volatile("cp.async.wait_group 0;")

#define LDSM_X4(r, addr) \
    asm volatile("ldmatrix.sync.aligned.m8n8.x4.shared.b16 {%0,%1,%2,%3},[%4];" \
                 : "=r"((r)[0]), "=r"((r)[1]), "=r"((r)[2]), "=r"((r)[3]) : "r"(addr))
#define LDSM_X4_T(r, addr) \
    asm volatile("ldmatrix.sync.aligned.m8n8.x4.trans.shared.b16 {%0,%1,%2,%3},[%4];" \
                 : "=r"((r)[0]), "=r"((r)[1]), "=r"((r)[2]), "=r"((r)[3]) : "r"(addr))

#define MMA_BF16(d, a, b) \
    asm volatile("mma.sync.aligned.m16n8k16.row.col.f32.bf16.bf16.f32 " \
                 "{%0,%1,%2,%3},{%4,%5,%6,%7},{%8,%9},{%0,%1,%2,%3};" \
                 : "+f"((d)[0]), "+f"((d)[1]), "+f"((d)[2]), "+f"((d)[3]) \
                 : "r"((a)[0]), "r"((a)[1]), "r"((a)[2]), "r"((a)[3]), \
                   "r"((b)[0]), "r"((b)[1]))

__device__ __forceinline__ float sigf(float x) { return 1.0f / (1.0f + expf(-x)); }

__device__ __forceinline__ unsigned ld_acq_u32(const unsigned* p)
{
    unsigned v;
    asm volatile("ld.acquire.gpu.global.b32 %0,[%1];" : "=r"(v) : "l"(p) : "memory");
    return v;
}

// Grid-wide barrier: monotonic counter, release-arrive / acquire-spin.
__device__ __forceinline__ void grid_bar(int t)
{
    __threadfence();                 // make this thread's stores device-visible
    __syncthreads();                 // all CTA threads have fenced
    if (threadIdx.x == 0) {
        atomicAdd(&g_count, 1u);
        const unsigned target = (unsigned)NCTA * (unsigned)(t + 1);
        while (ld_acq_u32(&g_count) < target) {
            __nanosleep(32);
        }
    }
    __syncthreads();
}

// ---------------------------------------------------------------------------
// Prep kernels
// ---------------------------------------------------------------------------
__global__ void init_state()
{
    int i = blockIdx.x * blockDim.x + threadIdx.x;
    if (i == 0) g_count = 0u;
    if (i < BB * HH) {
        g_h[0][i] = 0.0f;  g_c[0][i] = 0.0f;
        __nv_bfloat16 z = __float2bfloat16(0.0f);
        g_hhi[0][i] = z; g_hlo[0][i] = z; g_chi[0][i] = z; g_clo[0][i] = z;
    }
}

// x[b][t][k] -> Axhi/Axlo[(t*B+b)][k]
__global__ void convert_x(const float* __restrict__ x)
{
    size_t idx = (size_t)blockIdx.x * blockDim.x + threadIdx.x;
    if (idx >= (size_t)SS * BB * DD) return;
    int k = (int)(idx & (DD - 1));
    int m = (int)(idx >> 9);
    int b = m & (BB - 1);
    int t = m >> 8;
    float v = x[((size_t)b * SS + t) * DD + k];
    __nv_bfloat16 hi = __float2bfloat16(v);
    g_Axhi[idx] = hi;
    g_Axlo[idx] = __float2bfloat16(v - __bfloat162float(hi));
}

// Wstack[1536][2048] from Wi,Wf,Wog,Wc ([512][512] each)
__global__ void prep_wstack(const float* __restrict__ Wi, const float* __restrict__ Wf,
                            const float* __restrict__ Wog, const float* __restrict__ Wc)
{
    size_t idx = (size_t)blockIdx.x * blockDim.x + threadIdx.x;
    if (idx >= (size_t)KE * G4) return;
    int n = (int)(idx % G4);
    int k = (int)(idx / G4);
    int g = n >> 9;
    int j = n & (HH - 1);
    const float* src = (g == 0) ? Wi : (g == 1) ? Wf : (g == 2) ? Wog : Wc;
    float v = src[(size_t)(k & (HH - 1)) * HH + j];
    __nv_bfloat16 hi = __float2bfloat16(v);
    __nv_bfloat16 out;
    if (k < 512)       out = hi;
    else if (k < 1024) out = __float2bfloat16(v - __bfloat162float(hi));
    else               out = hi;
    g_Wstack[idx] = out;
}

// Ustack[1536][2560] from Ui,Uf,Uog,Uc,Wd
__global__ void prep_ustack(const float* __restrict__ Ui, const float* __restrict__ Uf,
                            const float* __restrict__ Uog, const float* __restrict__ Uc,
                            const float* __restrict__ Wd)
{
    size_t idx = (size_t)blockIdx.x * blockDim.x + threadIdx.x;
    if (idx >= (size_t)KE * N5) return;
    int n = (int)(idx % N5);
    int k = (int)(idx / N5);
    int g = n >> 9;
    int j = n & (HH - 1);
    const float* src = (g == 0) ? Ui : (g == 1) ? Uf : (g == 2) ? Uog : (g == 3) ? Uc : Wd;
    float v = src[(size_t)(k & (HH - 1)) * HH + j];
    __nv_bfloat16 hi = __float2bfloat16(v);
    __nv_bfloat16 out;
    if (k < 512)       out = hi;
    else if (k < 1024) out = __float2bfloat16(v - __bfloat162float(hi));
    else               out = hi;
    g_Ustack[idx] = out;
}

__global__ void prep_bias(const float* __restrict__ bi, const float* __restrict__ bf,
                          const float* __restrict__ bog, const float* __restrict__ bc)
{
    int n = blockIdx.x * blockDim.x + threadIdx.x;
    if (n >= G4) return;
    int g = n >> 9, j = n & (HH - 1);
    const float* src = (g == 0) ? bi : (g == 1) ? bf : (g == 2) ? bog : bc;
    g_bstack[n] = src[j];
}

// ---------------------------------------------------------------------------
// Precompute GEMM: g_gx[m][n] = Astack[m][:] @ Wstack[:][n] + bstack[n]
// M=131072, N=2048, K=1536.  CTA tile 128x64, 8 warps (4m x 2n), warp 32x32.
// ---------------------------------------------------------------------------
__global__ void __launch_bounds__(256) gemm_pre()
{
    __shared__ __nv_bfloat16 As[2][128][40];
    __shared__ __nv_bfloat16 Bs[2][32][72];

    const int m0 = blockIdx.x * 128;
    const int n0 = blockIdx.y * 64;
    const int tid = threadIdx.x;
    const int warp = tid >> 5, lane = tid & 31;
    const int wm = warp & 3, wn = warp >> 2;

    const int lrow = (lane & 7) + ((lane >> 3) & 1) * 8;
    const int lcol = (lane >> 4) * 8;

    float acc[2][4][4];
    #pragma unroll
    for (int a = 0; a < 2; a++)
        #pragma unroll
        for (int b = 0; b < 4; b++)
            #pragma unroll
            for (int c = 0; c < 4; c++) acc[a][b][c] = 0.0f;

    const int ar0 = (tid)       >> 2, ac0 = (tid & 3) * 8;
    const int ar1 = (tid + 256) >> 2;
    const int br  = tid >> 3,        bc = (tid & 7) * 8;

    auto load_stage = [&](int st, int kk) {
        const __nv_bfloat16* aBase = (kk < 1024) ? g_Axhi : g_Axlo;
        int acol = (kk & 511);
        CP_ASYNC16(smem_u32(&As[st][ar0][ac0]),
                   aBase + (size_t)(m0 + ar0) * DD + acol + ac0);
        CP_ASYNC16(smem_u32(&As[st][ar1][ac0]),
                   aBase + (size_t)(m0 + ar1) * DD + acol + ac0);
        CP_ASYNC16(smem_u32(&Bs[st][br][bc]),
                   g_Wstack + (size_t)(kk + br) * G4 + n0 + bc);
    };

    load_stage(0, 0);
    CP_COMMIT;

    for (int it = 0; it < NK; ++it) {
        if (it + 1 < NK) { load_stage((it + 1) & 1, (it + 1) * 32); CP_COMMIT; CP_WAIT1; }
        else            { CP_WAIT0; }
        __syncthreads();

        const int st = it & 1;
        #pragma unroll
        for (int kh = 0; kh < 2; kh++) {
            const int kb = kh * 16;
            unsigned afr[2][4], bfr[2][4];
            #pragma unroll
            for (int mt = 0; mt < 2; mt++)
                LDSM_X4(afr[mt], smem_u32(&As[st][wm * 32 + mt * 16 + lrow][kb + lcol]));
            #pragma unroll
            for (int nt = 0; nt < 2; nt++)
                LDSM_X4_T(bfr[nt], smem_u32(&Bs[st][kb + lrow][wn * 32 + nt * 16 + lcol]));
            #pragma unroll
            for (int mt = 0; mt < 2; mt++)
                #pragma unroll
                for (int nx = 0; nx < 4; nx++)
                    MMA_BF16(acc[mt][nx], afr[mt], &bfr[nx >> 1][(nx & 1) * 2]);
        }
        __syncthreads();
    }

    const int qrow = lane >> 2, qcol = (lane & 3) * 2;
    #pragma unroll
    for (int mt = 0; mt < 2; mt++) {
        #pragma unroll
        for (int rr = 0; rr < 2; rr++) {
            int m = m0 + wm * 32 + mt * 16 + qrow + rr * 8;
            #pragma unroll
            for (int nx = 0; nx < 4; nx++) {
                int n = n0 + wn * 32 + nx * 8 + qcol;
                float2 bv = *(const float2*)&g_bstack[n];
                float2 v = make_float2(acc[mt][nx][rr * 2 + 0] + bv.x,
                                       acc[mt][nx][rr * 2 + 1] + bv.y);
                *(float2*)&g_gx[(size_t)m * G4 + n] = v;
            }
        }
    }
}

// ---------------------------------------------------------------------------
// Persistent TLSTM scan: ONE launch runs all 512 steps.
// Grid (8,16) = 128 CTAs (all co-resident), 128 threads each.
// Dynamic smem: hs/cs/Bsh, 3 stages, rows padded to 40 bf16 (80B, 16B-aligned
// for cp.async + ldmatrix; this alignment is what Round 4 broke).
// ---------------------------------------------------------------------------
__global__ void __launch_bounds__(128, 1) tlstm_scan(
    const float* __restrict__ timep, const float* __restrict__ bd)
{
    extern __shared__ __nv_bfloat16 dyn[];
    // hs[st][r][c]  = dyn[HS_OFF + st*32*PAD + r*PAD + c]
    // cs[st][r][c]  = dyn[CS_OFF + st*32*PAD + r*PAD + c]
    // Bsh[st][g][r][c] = dyn[BS_OFF + ((st*5 + g)*32 + r)*PAD + c]

    const int m0 = blockIdx.x * 32;
    const int j0 = blockIdx.y * 32;
    const int tid = threadIdx.x;
    const int warp = tid >> 5, lane = tid & 31;
    const int wm = warp & 1, wj = warp >> 1;

    const int lrow = (lane & 7) + ((lane >> 3) & 1) * 8;
    const int lcol = (lane >> 4) * 8;
    const int qrow = lane >> 2, qcol = (lane & 3) * 2;

    const int arow = tid >> 2, acol = (tid & 3) * 8;

    for (int t = 0; t < SS; ++t) {
        const int pp = t & 1;
        const __nv_bfloat16* hhi = g_hhi[pp];
        const __nv_bfloat16* hlo = g_hlo[pp];
        const __nv_bfloat16* chi = g_chi[pp];
        const __nv_bfloat16* clo = g_clo[pp];

        // L2 prefetch for epilogue operands (land during the K loop)
        {
            int rr = tid & 31;      // m row in tile
            int gg = tid >> 5;      // gate 0..3
            const float* p = g_gx + ((size_t)t * BB + m0 + rr) * G4 + gg * HH + j0;
            asm volatile("prefetch.global.L2 [%0];" :: "l"(p));
            if (tid < 32) {
                const float* pc = g_c[pp] + (size_t)(m0 + tid) * HH + j0;
                asm volatile("prefetch.global.L2 [%0];" :: "l"(pc));
            }
        }

        auto load_stage = [&](int st, int kk) {
            const __nv_bfloat16* hB = (kk < 1024) ? hhi : hlo;
            const __nv_bfloat16* cB = (kk < 1024) ? chi : clo;
            int pcol = (kk & 511) + acol;
            CP_ASYNC16(smem_u32(&dyn[HS_OFF + (st * 32 + arow) * PAD + acol]),
                       hB + (size_t)(m0 + arow) * HH + pcol);
            CP_ASYNC16(smem_u32(&dyn[CS_OFF + (st * 32 + arow) * PAD + acol]),
                       cB + (size_t)(m0 + arow) * HH + pcol);
            #pragma unroll
            for (int g = 0; g < 5; g++)
                CP_ASYNC16(smem_u32(&dyn[BS_OFF + (((st * 5 + g) * 32) + arow) * PAD + acol]),
                           g_Ustack + (size_t)(kk + arow) * N5 + g * HH + j0 + acol);
        };

        float accG[4][2][4];
        float accD[2][4];
        #pragma unroll
        for (int g = 0; g < 4; g++)
            #pragma unroll
            for (int n = 0; n < 2; n++)
                #pragma unroll
                for (int c = 0; c < 4; c++) accG[g][n][c] = 0.0f;
        #pragma unroll
        for (int n = 0; n < 2; n++)
            #pragma unroll
            for (int c = 0; c < 4; c++) accD[n][c] = 0.0f;

        // pipeline prologue: stages 0, 1
        load_stage(0, 0);  CP_COMMIT;
        load_stage(1, 32); CP_COMMIT;

        int stC = 0;       // compute stage
        int stL = 2;       // next load stage
        for (int it = 0; it < NK; ++it) {
            CP_WAIT1;                      // stage it landed (per-thread)
            __syncthreads();               // visible CTA-wide; stage stL free
            const int ld = it + 2;
            if (ld < NK) load_stage(stL, ld * 32);
            CP_COMMIT;                     // unconditional: keeps group counts aligned

            // batch all fragment loads, then all MMAs
            unsigned ah[2][4], ac[2][4], bf[2][5][4];
            #pragma unroll
            for (int kh = 0; kh < 2; kh++) {
                const int kb = kh * 16;
                LDSM_X4(ah[kh], smem_u32(&dyn[HS_OFF + (stC * 32 + wm * 16 + lrow) * PAD + kb + lcol]));
                LDSM_X4(ac[kh], smem_u32(&dyn[CS_OFF + (stC * 32 + wm * 16 + lrow) * PAD + kb + lcol]));
                #pragma unroll
                for (int g = 0; g < 5; g++)
                    LDSM_X4_T(bf[kh][g],
                        smem_u32(&dyn[BS_OFF + (((stC * 5 + g) * 32) + kb + lrow) * PAD + wj * 16 + lcol]));
            }
            #pragma unroll
            for (int kh = 0; kh < 2; kh++) {
                #pragma unroll
                for (int g = 0; g < 4; g++) {
                    MMA_BF16(accG[g][0], ah[kh], &bf[kh][g][0]);
                    MMA_BF16(accG[g][1], ah[kh], &bf[kh][g][2]);
                }
                MMA_BF16(accD[0], ac[kh], &bf[kh][4][0]);
                MMA_BF16(accD[1], ac[kh], &bf[kh][4][2]);
            }

            stC = (stC == 2) ? 0 : stC + 1;
            stL = (stL == 2) ? 0 : stL + 1;
        }

        // ---------------- elementwise TLSTM update epilogue ----------------
        const float* c_in  = g_c[pp];
        float*       h_out = g_h[pp ^ 1];
        float*       c_out = g_c[pp ^ 1];
        __nv_bfloat16* hhi_o = g_hhi[pp ^ 1];
        __nv_bfloat16* hlo_o = g_hlo[pp ^ 1];
        __nv_bfloat16* chi_o = g_chi[pp ^ 1];
        __nv_bfloat16* clo_o = g_clo[pp ^ 1];

        #pragma unroll
        for (int rr = 0; rr < 2; rr++) {
            const int m  = m0 + wm * 16 + qrow + rr * 8;
            const float tv = timep[(size_t)m * SS + t];
            const float Tf = 1.0f / logf(tv + 2.7183f);
            const float* gxrow = g_gx + ((size_t)t * BB + m) * G4;
            #pragma unroll
            for (int n8 = 0; n8 < 2; n8++) {
                const int j = j0 + wj * 16 + n8 * 8 + qcol;
                const float2 gxi = *(const float2*)&gxrow[0 * HH + j];
                const float2 gxf = *(const float2*)&gxrow[1 * HH + j];
                const float2 gxo = *(const float2*)&gxrow[2 * HH + j];
                const float2 gxc = *(const float2*)&gxrow[3 * HH + j];
                const float2 cp  = *(const float2*)&c_in[(size_t)m * HH + j];
                const float2 bdv = *(const float2*)&bd[j];

                float d0 = accD[n8][rr * 2 + 0], d1 = accD[n8][rr * 2 + 1];
                float cst0 = tanhf(d0 + bdv.x), cst1 = tanhf(d1 + bdv.y);
                float c10 = cp.x - cst0 + Tf * cst0;
                float c11 = cp.y - cst1 + Tf * cst1;

                float i0 = sigf(accG[0][n8][rr * 2 + 0] + gxi.x);
                float i1 = sigf(accG[0][n8][rr * 2 + 1] + gxi.y);
                float f0 = sigf(accG[1][n8][rr * 2 + 0] + gxf.x);
                float f1 = sigf(accG[1][n8][rr * 2 + 1] + gxf.y);
                float o0 = sigf(accG[2][n8][rr * 2 + 0] + gxo.x);
                float o1 = sigf(accG[2][n8][rr * 2 + 1] + gxo.y);
                float n0v = tanhf(accG[3][n8][rr * 2 + 0] + gxc.x);
                float n1v = tanhf(accG[3][n8][rr * 2 + 1] + gxc.y);

                float cn0 = f0 * c10 + i0 * n0v;
                float cn1 = f1 * c11 + i1 * n1v;
                float hn0 = o0 * tanhf(cn0);
                float hn1 = o1 * tanhf(cn1);

                size_t off = (size_t)m * HH + j;
                *(float2*)&c_out[off] = make_float2(cn0, cn1);
                *(float2*)&h_out[off] = make_float2(hn0, hn1);

                __nv_bfloat16 ch0 = __float2bfloat16(cn0), ch1 = __float2bfloat16(cn1);
                __nv_bfloat16 hh0 = __float2bfloat16(hn0), hh1 = __float2bfloat16(hn1);
                *(__nv_bfloat162*)&chi_o[off] = __nv_bfloat162(ch0, ch1);
                *(__nv_bfloat162*)&clo_o[off] = __nv_bfloat162(
                    __float2bfloat16(cn0 - __bfloat162float(ch0)),
                    __float2bfloat16(cn1 - __bfloat162float(ch1)));
                *(__nv_bfloat162*)&hhi_o[off] = __nv_bfloat162(hh0, hh1);
                *(__nv_bfloat162*)&hlo_o[off] = __nv_bfloat162(
                    __float2bfloat16(hn0 - __bfloat162float(hh0)),
                    __float2bfloat16(hn1 - __bfloat162float(hh1)));
            }
        }

        grid_bar(t);
    }
}

// ---------------------------------------------------------------------------
// Output head: out[b,:] = relu(h_last[b,:] @ Wo + bo) @ Ws + bs
// ---------------------------------------------------------------------------
__global__ void head_kernel(const float* __restrict__ Wo, const float* __restrict__ bo,
                            const float* __restrict__ Ws, const float* __restrict__ bs,
                            float* __restrict__ out)
{
    __shared__ float hrow[HH];
    __shared__ float fc[FCC];
    const int b = blockIdx.x;
    const float* h = g_h[0] + (size_t)b * HH;
    for (int k = threadIdx.x; k < HH; k += blockDim.x) hrow[k] = h[k];
    __syncthreads();

    const int j = threadIdx.x;  // blockDim == FCC == 64
    float s = bo[j];
    for (int k = 0; k < HH; k++) s += hrow[k] * Wo[(size_t)k * FCC + j];
    fc[j] = fmaxf(s, 0.0f);
    __syncthreads();

    if (j < OO) {
        float r = bs[j];
        for (int q = 0; q < FCC; q++) r += fc[q] * Ws[(size_t)q * OO + j];
        out[(size_t)b * OO + j] = r;
    }
}

// ---------------------------------------------------------------------------
extern "C" void kernel_launch(void* const* d_in, const int* in_sizes, int n_in,
                              void* d_out, int out_size)
{
    const float* x   = (const float*)d_in[0];
    const float* tmv = (const float*)d_in[1];
    const float* Wi  = (const float*)d_in[2];
    const float* Ui  = (const float*)d_in[3];
    const float* bi  = (const float*)d_in[4];
    const float* Wf  = (const float*)d_in[5];
    const float* Uf  = (const float*)d_in[6];
    const float* bf  = (const float*)d_in[7];
    const float* Wog = (const float*)d_in[8];
    const float* Uog = (const float*)d_in[9];
    const float* bog = (const float*)d_in[10];
    const float* Wc  = (const float*)d_in[11];
    const float* Uc  = (const float*)d_in[12];
    const float* bc  = (const float*)d_in[13];
    const float* Wd  = (const float*)d_in[14];
    const float* bd  = (const float*)d_in[15];
    const float* Wo  = (const float*)d_in[16];
    const float* bo  = (const float*)d_in[17];
    const float* Ws  = (const float*)d_in[18];
    const float* bs  = (const float*)d_in[19];
    float* out = (float*)d_out;

    // opt-in to >48KB dynamic smem for the scan kernel (host attr, capture-safe)
    static bool attr_done = false;
    if (!attr_done) {
        cudaFuncSetAttribute(tlstm_scan,
                             cudaFuncAttributeMaxDynamicSharedMemorySize,
                             SCAN_SMEM_BYTES);
        attr_done = true;
    }

    init_state<<<(BB * HH + 255) / 256, 256>>>();

    {   size_t n = (size_t)SS * BB * DD;
        convert_x<<<(unsigned)((n + 255) / 256), 256>>>(x); }
    {   size_t n = (size_t)KE * G4;
        prep_wstack<<<(unsigned)((n + 255) / 256), 256>>>(Wi, Wf, Wog, Wc); }
    {   size_t n = (size_t)KE * N5;
        prep_ustack<<<(unsigned)((n + 255) / 256), 256>>>(Ui, Uf, Uog, Uc, Wd); }
    prep_bias<<<(G4 + 255) / 256, 256>>>(bi, bf, bog, bc);

    dim3 gg(1024, 32);
    gemm_pre<<<gg, 256>>>();

    dim3 gs(8, 16);
    tlstm_scan<<<gs, 128, SCAN_SMEM_BYTES>>>(tmv, bd);

    // step 511 reads buffer 1, writes buffer 0 -> final state in buffer 0
    head_kernel<<<BB, FCC>>>(Wo, bo, Ws, bs, out);
}

// round 6
// speedup vs baseline: 2.0434x; 1.0023x over previous
#include <cuda_runtime.h>
#include <cuda_bf16.h>
#include <math.h>

#define BB   256
#define SS   512
#define DD   512
#define HH   512
#define FCC  64
#define OO   2
#define G4   2048          // 4*H
#define KE   1536          // tripled K (hi*hi, hi*lo, lo*hi)
#define NK   48            // KE / 32
#define N5   2560          // 5*H
#define NCTA 128           // scan grid (8 x 16)

// scan kernel dynamic smem layout (bf16 elements), row pad 40 (80B, 16B-aligned)
#define PAD      40
#define HS_OFF   0                      // [3][32][40]
#define CS_OFF   (3 * 32 * PAD)         // [3][32][40]
#define BS_OFF   (2 * 3 * 32 * PAD)     // [3][5][32][40]
#define STAGE_ELEMS (2 * 3 * 32 * PAD + 3 * 5 * 32 * PAD)      // 26880 bf16
#define RED_FOFF  (STAGE_ELEMS / 2)                             // float index of red area
#define RED_FLOATS (8 * 32 * 21)                                // 5376 floats
#define SCAN_SMEM_BYTES (STAGE_ELEMS * 2 + RED_FLOATS * 4)      // 75264 B

// ---------------------------------------------------------------------------
// Static device scratch (allocation-free contract)
// ---------------------------------------------------------------------------
__device__ float         g_gx[(size_t)SS * BB * G4];        // [t*B+b][4H] preacts + bias
__device__ __nv_bfloat16 g_Axhi[(size_t)SS * BB * DD];      // A planes for precompute
__device__ __nv_bfloat16 g_Axlo[(size_t)SS * BB * DD];
__device__ __nv_bfloat16 g_Wstack[(size_t)KE * G4];         // [1536][2048]  (hi;lo;hi)
__device__ __nv_bfloat16 g_Ustack[(size_t)KE * N5];         // [1536][2560]  (hi;lo;hi)
__device__ float         g_bstack[G4];
__device__ float         g_h[2][BB * HH];
__device__ float         g_c[2][BB * HH];
__device__ __nv_bfloat16 g_hhi[2][BB * HH];
__device__ __nv_bfloat16 g_hlo[2][BB * HH];
__device__ __nv_bfloat16 g_chi[2][BB * HH];
__device__ __nv_bfloat16 g_clo[2][BB * HH];
__device__ unsigned      g_count;                            // grid barrier counter

// ---------------------------------------------------------------------------
// PTX helpers
// ---------------------------------------------------------------------------
__device__ __forceinline__ unsigned smem_u32(const void* p)
{
    return (unsigned)__cvta_generic_to_shared(p);
}

#define CP_ASYNC16(dst_u32, src_ptr) \
    asm volatile("cp.async.cg.shared.global [%0],[%1],16;" :: "r"(dst_u32), "l"(src_ptr))
#define CP_COMMIT   asm volatile("cp.async.commit_group;")
#define CP_WAIT1    asm volatile("cp.async.wait_group 1;")
#define CP_WAIT0    asm volatile("cp.async.wait_group 0;")

#define LDSM_X4(r, addr) \
    asm volatile("ldmatrix.sync.aligned.m8n8.x4.shared.b16 {%0,%1,%2,%3},[%4];" \
                 : "=r"((r)[0]), "=r"((r)[1]), "=r"((r)[2]), "=r"((r)[3]) : "r"(addr))
#define LDSM_X4_T(r, addr) \
    asm volatile("ldmatrix.sync.aligned.m8n8.x4.trans.shared.b16 {%0,%1,%2,%3},[%4];" \
                 : "=r"((r)[0]), "=r"((r)[1]), "=r"((r)[2]), "=r"((r)[3]) : "r"(addr))

#define MMA_BF16(d, a, b) \
    asm volatile("mma.sync.aligned.m16n8k16.row.col.f32.bf16.bf16.f32 " \
                 "{%0,%1,%2,%3},{%4,%5,%6,%7},{%8,%9},{%0,%1,%2,%3};" \
                 : "+f"((d)[0]), "+f"((d)[1]), "+f"((d)[2]), "+f"((d)[3]) \
                 : "r"((a)[0]), "r"((a)[1]), "r"((a)[2]), "r"((a)[3]), \
                   "r"((b)[0]), "r"((b)[1]))

__device__ __forceinline__ float sigf(float x) { return 1.0f / (1.0f + expf(-x)); }

__device__ __forceinline__ unsigned ld_acq_u32(const unsigned* p)
{
    unsigned v;
    asm volatile("ld.acquire.gpu.global.b32 %0,[%1];" : "=r"(v) : "l"(p) : "memory");
    return v;
}

// Grid-wide barrier: monotonic counter, release-arrive / acquire-spin.
__device__ __forceinline__ void grid_bar(int t)
{
    __threadfence();
    __syncthreads();
    if (threadIdx.x == 0) {
        atomicAdd(&g_count, 1u);
        const unsigned target = (unsigned)NCTA * (unsigned)(t + 1);
        while (ld_acq_u32(&g_count) < target) {
            __nanosleep(32);
        }
    }
    __syncthreads();
}

// ---------------------------------------------------------------------------
// Prep kernels
// ---------------------------------------------------------------------------
__global__ void init_state()
{
    int i = blockIdx.x * blockDim.x + threadIdx.x;
    if (i == 0) g_count = 0u;
    if (i < BB * HH) {
        g_h[0][i] = 0.0f;  g_c[0][i] = 0.0f;
        __nv_bfloat16 z = __float2bfloat16(0.0f);
        g_hhi[0][i] = z; g_hlo[0][i] = z; g_chi[0][i] = z; g_clo[0][i] = z;
    }
}

__global__ void convert_x(const float* __restrict__ x)
{
    size_t idx = (size_t)blockIdx.x * blockDim.x + threadIdx.x;
    if (idx >= (size_t)SS * BB * DD) return;
    int k = (int)(idx & (DD - 1));
    int m = (int)(idx >> 9);
    int b = m & (BB - 1);
    int t = m >> 8;
    float v = x[((size_t)b * SS + t) * DD + k];
    __nv_bfloat16 hi = __float2bfloat16(v);
    g_Axhi[idx] = hi;
    g_Axlo[idx] = __float2bfloat16(v - __bfloat162float(hi));
}

__global__ void prep_wstack(const float* __restrict__ Wi, const float* __restrict__ Wf,
                            const float* __restrict__ Wog, const float* __restrict__ Wc)
{
    size_t idx = (size_t)blockIdx.x * blockDim.x + threadIdx.x;
    if (idx >= (size_t)KE * G4) return;
    int n = (int)(idx % G4);
    int k = (int)(idx / G4);
    int g = n >> 9;
    int j = n & (HH - 1);
    const float* src = (g == 0) ? Wi : (g == 1) ? Wf : (g == 2) ? Wog : Wc;
    float v = src[(size_t)(k & (HH - 1)) * HH + j];
    __nv_bfloat16 hi = __float2bfloat16(v);
    __nv_bfloat16 out;
    if (k < 512)       out = hi;
    else if (k < 1024) out = __float2bfloat16(v - __bfloat162float(hi));
    else               out = hi;
    g_Wstack[idx] = out;
}

__global__ void prep_ustack(const float* __restrict__ Ui, const float* __restrict__ Uf,
                            const float* __restrict__ Uog, const float* __restrict__ Uc,
                            const float* __restrict__ Wd)
{
    size_t idx = (size_t)blockIdx.x * blockDim.x + threadIdx.x;
    if (idx >= (size_t)KE * N5) return;
    int n = (int)(idx % N5);
    int k = (int)(idx / N5);
    int g = n >> 9;
    int j = n & (HH - 1);
    const float* src = (g == 0) ? Ui : (g == 1) ? Uf : (g == 2) ? Uog : (g == 3) ? Uc : Wd;
    float v = src[(size_t)(k & (HH - 1)) * HH + j];
    __nv_bfloat16 hi = __float2bfloat16(v);
    __nv_bfloat16 out;
    if (k < 512)       out = hi;
    else if (k < 1024) out = __float2bfloat16(v - __bfloat162float(hi));
    else               out = hi;
    g_Ustack[idx] = out;
}

__global__ void prep_bias(const float* __restrict__ bi, const float* __restrict__ bf,
                          const float* __restrict__ bog, const float* __restrict__ bc)
{
    int n = blockIdx.x * blockDim.x + threadIdx.x;
    if (n >= G4) return;
    int g = n >> 9, j = n & (HH - 1);
    const float* src = (g == 0) ? bi : (g == 1) ? bf : (g == 2) ? bog : bc;
    g_bstack[n] = src[j];
}

// ---------------------------------------------------------------------------
// Precompute GEMM: g_gx[m][n] = Astack[m][:] @ Wstack[:][n] + bstack[n]
// M=131072, N=2048, K=1536.  CTA tile 128x128, 8 warps (4m x 2n), warp 32x64.
// Grid (16 n-blocks = x FAST, 1024 m-blocks = y): wave holds all n-blocks,
// so B stays L2-resident and A streams from DRAM exactly once.
// ---------------------------------------------------------------------------
__global__ void __launch_bounds__(256) gemm_pre()
{
    __shared__ __nv_bfloat16 As[2][128][40];
    __shared__ __nv_bfloat16 Bs[2][32][136];

    const int n0 = blockIdx.x * 128;
    const int m0 = blockIdx.y * 128;
    const int tid = threadIdx.x;
    const int warp = tid >> 5, lane = tid & 31;
    const int wm = warp & 3, wn = warp >> 2;

    const int lrow = (lane & 7) + ((lane >> 3) & 1) * 8;
    const int lcol = (lane >> 4) * 8;

    float acc[2][8][4];
    #pragma unroll
    for (int a = 0; a < 2; a++)
        #pragma unroll
        for (int b = 0; b < 8; b++)
            #pragma unroll
            for (int c = 0; c < 4; c++) acc[a][b][c] = 0.0f;

    // A chunks: 512 per stage (row = c>>2, col8 = c&3); threads take c = tid, tid+256
    // B chunks: 512 per stage (row = c>>4, col8 = c&15); same split
    auto load_stage = [&](int st, int kk) {
        const __nv_bfloat16* aBase = (kk < 1024) ? g_Axhi : g_Axlo;
        const int acolk = (kk & 511);
        #pragma unroll
        for (int r = 0; r < 2; r++) {
            int c  = tid + r * 256;
            int arow = c >> 2, ac8 = (c & 3) * 8;
            CP_ASYNC16(smem_u32(&As[st][arow][ac8]),
                       aBase + (size_t)(m0 + arow) * DD + acolk + ac8);
            int brow = c >> 4, bc8 = (c & 15) * 8;
            CP_ASYNC16(smem_u32(&Bs[st][brow][bc8]),
                       g_Wstack + (size_t)(kk + brow) * G4 + n0 + bc8);
        }
    };

    load_stage(0, 0);
    CP_COMMIT;

    for (int it = 0; it < NK; ++it) {
        if (it + 1 < NK) { load_stage((it + 1) & 1, (it + 1) * 32); CP_COMMIT; CP_WAIT1; }
        else            { CP_WAIT0; }
        __syncthreads();

        const int st = it & 1;
        #pragma unroll
        for (int kh = 0; kh < 2; kh++) {
            const int kb = kh * 16;
            unsigned afr[2][4], bfr[4][4];
            #pragma unroll
            for (int mt = 0; mt < 2; mt++)
                LDSM_X4(afr[mt], smem_u32(&As[st][wm * 32 + mt * 16 + lrow][kb + lcol]));
            #pragma unroll
            for (int nt = 0; nt < 4; nt++)
                LDSM_X4_T(bfr[nt], smem_u32(&Bs[st][kb + lrow][wn * 64 + nt * 16 + lcol]));
            #pragma unroll
            for (int mt = 0; mt < 2; mt++)
                #pragma unroll
                for (int nx = 0; nx < 8; nx++)
                    MMA_BF16(acc[mt][nx], afr[mt], &bfr[nx >> 1][(nx & 1) * 2]);
        }
        __syncthreads();
    }

    const int qrow = lane >> 2, qcol = (lane & 3) * 2;
    #pragma unroll
    for (int mt = 0; mt < 2; mt++) {
        #pragma unroll
        for (int rr = 0; rr < 2; rr++) {
            int m = m0 + wm * 32 + mt * 16 + qrow + rr * 8;
            #pragma unroll
            for (int nx = 0; nx < 8; nx++) {
                int n = n0 + wn * 64 + nx * 8 + qcol;
                float2 bv = *(const float2*)&g_bstack[n];
                float2 v = make_float2(acc[mt][nx][rr * 2 + 0] + bv.x,
                                       acc[mt][nx][rr * 2 + 1] + bv.y);
                *(float2*)&g_gx[(size_t)m * G4 + n] = v;
            }
        }
    }
}

// ---------------------------------------------------------------------------
// Persistent TLSTM scan, 256 threads, split-K across warp pairs.
// Warps: wm = warp&1 (16-row half), wj = (warp>>1)&1 (16-col half),
//        wk = warp>>2  (k16-chunk within each 32-wide K iter).
// Warp pair (w, w^4) holds partial sums for the same 16x16 tile; the pair
// exchanges output halves via smem, then each warp runs the epilogue for
// its own 8-row group (rr = wk).
// ---------------------------------------------------------------------------
__global__ void __launch_bounds__(256, 1) tlstm_scan(
    const float* __restrict__ timep, const float* __restrict__ bd)
{
    extern __shared__ __nv_bfloat16 dyn[];
    float* red = (float*)dyn + RED_FOFF;

    const int m0 = blockIdx.x * 32;
    const int j0 = blockIdx.y * 32;
    const int tid = threadIdx.x;
    const int warp = tid >> 5, lane = tid & 31;
    const int wm = warp & 1, wj = (warp >> 1) & 1, wk = warp >> 2;

    const int lrow = (lane & 7) + ((lane >> 3) & 1) * 8;
    const int lcol = (lane >> 4) * 8;
    const int qrow = lane >> 2, qcol = (lane & 3) * 2;

    for (int t = 0; t < SS; ++t) {
        const int pp = t & 1;
        const __nv_bfloat16* hhi = g_hhi[pp];
        const __nv_bfloat16* hlo = g_hlo[pp];
        const __nv_bfloat16* chi = g_chi[pp];
        const __nv_bfloat16* clo = g_clo[pp];

        // L2 prefetch of all epilogue cache lines (128 gx lines + 32 c lines)
        if (tid < 128) {
            int rr = tid & 31, gg = tid >> 5;
            const float* p = g_gx + ((size_t)t * BB + m0 + rr) * G4 + gg * HH + j0;
            asm volatile("prefetch.global.L2 [%0];" :: "l"(p));
            if (tid < 32) {
                const float* pc = g_c[pp] + (size_t)(m0 + tid) * HH + j0;
                asm volatile("prefetch.global.L2 [%0];" :: "l"(pc));
            }
        }

        // 7 tiles of 32x32 bf16 per stage = 896 16B chunks; threads <128 take
        // {hs, B0, B2, B4}, threads >=128 take {cs, B1, B3}.
        auto load_stage = [&](int st, int kk) {
            const int pk = (kk & 511);
            if (tid < 128) {
                const __nv_bfloat16* hB = (kk < 1024) ? hhi : hlo;
                int row = tid >> 2, c8 = (tid & 3) * 8;
                CP_ASYNC16(smem_u32(&dyn[HS_OFF + (st * 32 + row) * PAD + c8]),
                           hB + (size_t)(m0 + row) * HH + pk + c8);
                const __nv_bfloat16* ub = g_Ustack + (size_t)(kk + row) * N5 + j0 + c8;
                CP_ASYNC16(smem_u32(&dyn[BS_OFF + ((st * 5 + 0) * 32 + row) * PAD + c8]), ub + 0 * HH);
                CP_ASYNC16(smem_u32(&dyn[BS_OFF + ((st * 5 + 2) * 32 + row) * PAD + c8]), ub + 2 * HH);
                CP_ASYNC16(smem_u32(&dyn[BS_OFF + ((st * 5 + 4) * 32 + row) * PAD + c8]), ub + 4 * HH);
            } else {
                const __nv_bfloat16* cB = (kk < 1024) ? chi : clo;
                int u = tid - 128;
                int row = u >> 2, c8 = (u & 3) * 8;
                CP_ASYNC16(smem_u32(&dyn[CS_OFF + (st * 32 + row) * PAD + c8]),
                           cB + (size_t)(m0 + row) * HH + pk + c8);
                const __nv_bfloat16* ub = g_Ustack + (size_t)(kk + row) * N5 + j0 + c8;
                CP_ASYNC16(smem_u32(&dyn[BS_OFF + ((st * 5 + 1) * 32 + row) * PAD + c8]), ub + 1 * HH);
                CP_ASYNC16(smem_u32(&dyn[BS_OFF + ((st * 5 + 3) * 32 + row) * PAD + c8]), ub + 3 * HH);
            }
        };

        float accG[4][2][4];
        float accD[2][4];
        #pragma unroll
        for (int g = 0; g < 4; g++)
            #pragma unroll
            for (int n = 0; n < 2; n++)
                #pragma unroll
                for (int c = 0; c < 4; c++) accG[g][n][c] = 0.0f;
        #pragma unroll
        for (int n = 0; n < 2; n++)
            #pragma unroll
            for (int c = 0; c < 4; c++) accD[n][c] = 0.0f;

        load_stage(0, 0);  CP_COMMIT;
        load_stage(1, 32); CP_COMMIT;

        const int kb = wk * 16;     // this warp's k16 chunk within the 32-wide iter
        int stC = 0, stL = 2;
        for (int it = 0; it < NK; ++it) {
            CP_WAIT1;
            __syncthreads();
            const int ld = it + 2;
            if (ld < NK) load_stage(stL, ld * 32);
            CP_COMMIT;

            unsigned ah[4], ac[4], bf[5][4];
            LDSM_X4(ah, smem_u32(&dyn[HS_OFF + (stC * 32 + wm * 16 + lrow) * PAD + kb + lcol]));
            LDSM_X4(ac, smem_u32(&dyn[CS_OFF + (stC * 32 + wm * 16 + lrow) * PAD + kb + lcol]));
            #pragma unroll
            for (int g = 0; g < 5; g++)
                LDSM_X4_T(bf[g],
                    smem_u32(&dyn[BS_OFF + ((stC * 5 + g) * 32 + kb + lrow) * PAD + wj * 16 + lcol]));

            #pragma unroll
            for (int g = 0; g < 4; g++) {
                MMA_BF16(accG[g][0], ah, &bf[g][0]);
                MMA_BF16(accG[g][1], ah, &bf[g][2]);
            }
            MMA_BF16(accD[0], ac, &bf[4][0]);
            MMA_BF16(accD[1], ac, &bf[4][2]);

            stC = (stC == 2) ? 0 : stC + 1;
            stL = (stL == 2) ? 0 : stL + 1;
        }

        // ---- cross-pair reduction: ship the half we don't own ----
        {
            const int co = (1 - wk) * 2;                 // half this warp gives away
            float* myw = &red[(warp * 32 + lane) * 21];
            #pragma unroll
            for (int g = 0; g < 4; g++)
                #pragma unroll
                for (int n = 0; n < 2; n++) {
                    myw[g * 4 + n * 2 + 0] = accG[g][n][co + 0];
                    myw[g * 4 + n * 2 + 1] = accG[g][n][co + 1];
                }
            #pragma unroll
            for (int n = 0; n < 2; n++) {
                myw[16 + n * 2 + 0] = accD[n][co + 0];
                myw[16 + n * 2 + 1] = accD[n][co + 1];
            }
        }
        __syncthreads();
        const int c0 = wk * 2;                           // half this warp keeps
        {
            const float* pr = &red[((warp ^ 4) * 32 + lane) * 21];
            #pragma unroll
            for (int g = 0; g < 4; g++)
                #pragma unroll
                for (int n = 0; n < 2; n++) {
                    accG[g][n][c0 + 0] += pr[g * 4 + n * 2 + 0];
                    accG[g][n][c0 + 1] += pr[g * 4 + n * 2 + 1];
                }
            #pragma unroll
            for (int n = 0; n < 2; n++) {
                accD[n][c0 + 0] += pr[16 + n * 2 + 0];
                accD[n][c0 + 1] += pr[16 + n * 2 + 1];
            }
        }

        // ---------------- elementwise TLSTM update (rr = wk) ----------------
        const float* c_in  = g_c[pp];
        float*       h_out = g_h[pp ^ 1];
        float*       c_out = g_c[pp ^ 1];
        __nv_bfloat16* hhi_o = g_hhi[pp ^ 1];
        __nv_bfloat16* hlo_o = g_hlo[pp ^ 1];
        __nv_bfloat16* chi_o = g_chi[pp ^ 1];
        __nv_bfloat16* clo_o = g_clo[pp ^ 1];

        {
            const int m  = m0 + wm * 16 + wk * 8 + qrow;
            const float tv = timep[(size_t)m * SS + t];
            const float Tf = 1.0f / logf(tv + 2.7183f);
            const float* gxrow = g_gx + ((size_t)t * BB + m) * G4;
            #pragma unroll
            for (int n8 = 0; n8 < 2; n8++) {
                const int j = j0 + wj * 16 + n8 * 8 + qcol;
                const float2 gxi = *(const float2*)&gxrow[0 * HH + j];
                const float2 gxf = *(const float2*)&gxrow[1 * HH + j];
                const float2 gxo = *(const float2*)&gxrow[2 * HH + j];
                const float2 gxc = *(const float2*)&gxrow[3 * HH + j];
                const float2 cp  = *(const float2*)&c_in[(size_t)m * HH + j];
                const float2 bdv = *(const float2*)&bd[j];

                float d0 = accD[n8][c0 + 0], d1 = accD[n8][c0 + 1];
                float cst0 = tanhf(d0 + bdv.x), cst1 = tanhf(d1 + bdv.y);
                float c10 = cp.x - cst0 + Tf * cst0;
                float c11 = cp.y - cst1 + Tf * cst1;

                float i0 = sigf(accG[0][n8][c0 + 0] + gxi.x);
                float i1 = sigf(accG[0][n8][c0 + 1] + gxi.y);
                float f0 = sigf(accG[1][n8][c0 + 0] + gxf.x);
                float f1 = sigf(accG[1][n8][c0 + 1] + gxf.y);
                float o0 = sigf(accG[2][n8][c0 + 0] + gxo.x);
                float o1 = sigf(accG[2][n8][c0 + 1] + gxo.y);
                float n0v = tanhf(accG[3][n8][c0 + 0] + gxc.x);
                float n1v = tanhf(accG[3][n8][c0 + 1] + gxc.y);

                float cn0 = f0 * c10 + i0 * n0v;
                float cn1 = f1 * c11 + i1 * n1v;
                float hn0 = o0 * tanhf(cn0);
                float hn1 = o1 * tanhf(cn1);

                size_t off = (size_t)m * HH + j;
                *(float2*)&c_out[off] = make_float2(cn0, cn1);
                *(float2*)&h_out[off] = make_float2(hn0, hn1);

                __nv_bfloat16 ch0 = __float2bfloat16(cn0), ch1 = __float2bfloat16(cn1);
                __nv_bfloat16 hh0 = __float2bfloat16(hn0), hh1 = __float2bfloat16(hn1);
                *(__nv_bfloat162*)&chi_o[off] = __nv_bfloat162(ch0, ch1);
                *(__nv_bfloat162*)&clo_o[off] = __nv_bfloat162(
                    __float2bfloat16(cn0 - __bfloat162float(ch0)),
                    __float2bfloat16(cn1 - __bfloat162float(ch1)));
                *(__nv_bfloat162*)&hhi_o[off] = __nv_bfloat162(hh0, hh1);
                *(__nv_bfloat162*)&hlo_o[off] = __nv_bfloat162(
                    __float2bfloat16(hn0 - __bfloat162float(hh0)),
                    __float2bfloat16(hn1 - __bfloat162float(hh1)));
            }
        }

        grid_bar(t);
    }
}

// ---------------------------------------------------------------------------
// Output head: out[b,:] = relu(h_last[b,:] @ Wo + bo) @ Ws + bs
// ---------------------------------------------------------------------------
__global__ void head_kernel(const float* __restrict__ Wo, const float* __restrict__ bo,
                            const float* __restrict__ Ws, const float* __restrict__ bs,
                            float* __restrict__ out)
{
    __shared__ float hrow[HH];
    __shared__ float fc[FCC];
    const int b = blockIdx.x;
    const float* h = g_h[0] + (size_t)b * HH;
    for (int k = threadIdx.x; k < HH; k += blockDim.x) hrow[k] = h[k];
    __syncthreads();

    const int j = threadIdx.x;  // blockDim == FCC == 64
    float s = bo[j];
    for (int k = 0; k < HH; k++) s += hrow[k] * Wo[(size_t)k * FCC + j];
    fc[j] = fmaxf(s, 0.0f);
    __syncthreads();

    if (j < OO) {
        float r = bs[j];
        for (int q = 0; q < FCC; q++) r += fc[q] * Ws[(size_t)q * OO + j];
        out[(size_t)b * OO + j] = r;
    }
}

// ---------------------------------------------------------------------------
extern "C" void kernel_launch(void* const* d_in, const int* in_sizes, int n_in,
                              void* d_out, int out_size)
{
    const float* x   = (const float*)d_in[0];
    const float* tmv = (const float*)d_in[1];
    const float* Wi  = (const float*)d_in[2];
    const float* Ui  = (const float*)d_in[3];
    const float* bi  = (const float*)d_in[4];
    const float* Wf  = (const float*)d_in[5];
    const float* Uf  = (const float*)d_in[6];
    const float* bf  = (const float*)d_in[7];
    const float* Wog = (const float*)d_in[8];
    const float* Uog = (const float*)d_in[9];
    const float* bog = (const float*)d_in[10];
    const float* Wc  = (const float*)d_in[11];
    const float* Uc  = (const float*)d_in[12];
    const float* bc  = (const float*)d_in[13];
    const float* Wd  = (const float*)d_in[14];
    const float* bd  = (const float*)d_in[15];
    const float* Wo  = (const float*)d_in[16];
    const float* bo  = (const float*)d_in[17];
    const float* Ws  = (const float*)d_in[18];
    const float* bs  = (const float*)d_in[19];
    float* out = (float*)d_out;

    static bool attr_done = false;
    if (!attr_done) {
        cudaFuncSetAttribute(tlstm_scan,
                             cudaFuncAttributeMaxDynamicSharedMemorySize,
                             SCAN_SMEM_BYTES);
        attr_done = true;
    }

    init_state<<<(BB * HH + 255) / 256, 256>>>();

    {   size_t n = (size_t)SS * BB * DD;
        convert_x<<<(unsigned)((n + 255) / 256), 256>>>(x); }
    {   size_t n = (size_t)KE * G4;
        prep_wstack<<<(unsigned)((n + 255) / 256), 256>>>(Wi, Wf, Wog, Wc); }
    {   size_t n = (size_t)KE * N5;
        prep_ustack<<<(unsigned)((n + 255) / 256), 256>>>(Ui, Uf, Uog, Uc, Wd); }
    prep_bias<<<(G4 + 255) / 256, 256>>>(bi, bf, bog, bc);

    dim3 gg(16, 1024);      // x = n-blocks (fast) -> B stays L2-resident
    gemm_pre<<<gg, 256>>>();

    dim3 gs(8, 16);
    tlstm_scan<<<gs, 256, SCAN_SMEM_BYTES>>>(tmv, bd);

    head_kernel<<<BB, FCC>>>(Wo, bo, Ws, bs, out);
}

// round 9
// speedup vs baseline: 2.8120x; 1.3761x over previous
#include <cuda_runtime.h>
#include <cuda_fp16.h>
#include <math.h>
#include <stdint.h>

#define BB   256
#define SS   512
#define DD   512
#define HH   512
#define FCC  64
#define OO   2
#define G4   2048          // 4*H
#define KE   1024          // 2-plane fp16 split (hi | lo) against duplicated fp16 W
#define NK   32            // KE / 32 (scan K iters)
#define N5   2560          // 5*H
#define NCTA 128           // scan grid (8 x 16)

// ---- scan kernel dynamic smem layout (fp16 elements), row pad 40 ----
#define PAD      40
#define HS_OFF   0
#define CS_OFF   (3 * 32 * PAD)
#define BS_OFF   (2 * 3 * 32 * PAD)
#define STAGE_ELEMS (2 * 3 * 32 * PAD + 3 * 5 * 32 * PAD)
#define RED_FOFF  (STAGE_ELEMS / 2)
#define RED_FLOATS (8 * 32 * 21)
#define SCAN_SMEM_BYTES (STAGE_ELEMS * 2 + RED_FLOATS * 4)

// ---------------------------------------------------------------------------
// Static device scratch (allocation-free contract)
// ---------------------------------------------------------------------------
__device__ float   g_gx[(size_t)SS * BB * G4];
__device__ __half  g_Axhi[(size_t)SS * BB * DD];
__device__ __half  g_Axlo[(size_t)SS * BB * DD];
__device__ __half  g_Wstack[(size_t)KE * G4];      // [1024][2048] = [Wf; Wf]
__device__ __half  g_Ustack[(size_t)KE * N5];      // [1024][2560] = [Uf; Uf]
__device__ float   g_bstack[G4];
__device__ float   g_h[2][BB * HH];
__device__ float   g_c[2][BB * HH];
__device__ __half  g_hhi[2][BB * HH];
__device__ __half  g_hlo[2][BB * HH];
__device__ __half  g_chi[2][BB * HH];
__device__ __half  g_clo[2][BB * HH];
__device__ unsigned g_count;

// ---------------------------------------------------------------------------
// PTX helpers
// ---------------------------------------------------------------------------
__device__ __forceinline__ unsigned smem_u32(const void* p)
{
    return (unsigned)__cvta_generic_to_shared(p);
}

#define CP_ASYNC16(dst_u32, src_ptr) \
    asm volatile("cp.async.cg.shared.global [%0],[%1],16;" :: "r"(dst_u32), "l"(src_ptr))
#define CP_COMMIT   asm volatile("cp.async.commit_group;")
#define CP_WAIT1    asm volatile("cp.async.wait_group 1;")
#define CP_WAIT0    asm volatile("cp.async.wait_group 0;")

#define LDSM_X4(r, addr) \
    asm volatile("ldmatrix.sync.aligned.m8n8.x4.shared.b16 {%0,%1,%2,%3},[%4];" \
                 : "=r"((r)[0]), "=r"((r)[1]), "=r"((r)[2]), "=r"((r)[3]) : "r"(addr))
#define LDSM_X4_T(r, addr) \
    asm volatile("ldmatrix.sync.aligned.m8n8.x4.trans.shared.b16 {%0,%1,%2,%3},[%4];" \
                 : "=r"((r)[0]), "=r"((r)[1]), "=r"((r)[2]), "=r"((r)[3]) : "r"(addr))

#define MMA_F16(d, a, b) \
    asm volatile("mma.sync.aligned.m16n8k16.row.col.f32.f16.f16.f32 " \
                 "{%0,%1,%2,%3},{%4,%5,%6,%7},{%8,%9},{%0,%1,%2,%3};" \
                 : "+f"((d)[0]), "+f"((d)[1]), "+f"((d)[2]), "+f"((d)[3]) \
                 : "r"((a)[0]), "r"((a)[1]), "r"((a)[2]), "r"((a)[3]), \
                   "r"((b)[0]), "r"((b)[1]))

__device__ __forceinline__ float sigf(float x) { return 1.0f / (1.0f + expf(-x)); }

__device__ __forceinline__ unsigned ld_acq_u32(const unsigned* p)
{
    unsigned v;
    asm volatile("ld.acquire.gpu.global.b32 %0,[%1];" : "=r"(v) : "l"(p) : "memory");
    return v;
}

__device__ __forceinline__ void grid_bar(int t)
{
    __threadfence();
    __syncthreads();
    if (threadIdx.x == 0) {
        atomicAdd(&g_count, 1u);
        const unsigned target = (unsigned)NCTA * (unsigned)(t + 1);
        while (ld_acq_u32(&g_count) < target) {
            __nanosleep(32);
        }
    }
    __syncthreads();
}

// ---------------------------------------------------------------------------
// Prep kernels
// ---------------------------------------------------------------------------
__global__ void init_state()
{
    int i = blockIdx.x * blockDim.x + threadIdx.x;
    if (i == 0) g_count = 0u;
    if (i < BB * HH) {
        g_h[0][i] = 0.0f;  g_c[0][i] = 0.0f;
        __half z = __float2half_rn(0.0f);
        g_hhi[0][i] = z; g_hlo[0][i] = z; g_chi[0][i] = z; g_clo[0][i] = z;
    }
}

// x[b][t][k] -> fp16 hi/lo planes at [(t*B+b)][k]
__global__ void convert_x(const float* __restrict__ x)
{
    size_t idx = (size_t)blockIdx.x * blockDim.x + threadIdx.x;
    if (idx >= (size_t)SS * BB * DD) return;
    int k = (int)(idx & (DD - 1));
    int m = (int)(idx >> 9);
    int b = m & (BB - 1);
    int t = m >> 8;
    float v = x[((size_t)b * SS + t) * DD + k];
    __half hi = __float2half_rn(v);
    g_Axhi[idx] = hi;
    g_Axlo[idx] = __float2half_rn(v - __half2float(hi));
}

// Wstack[1024][2048]: BOTH K-halves hold fp16(W) (A planes sum to x)
__global__ void prep_wstack(const float* __restrict__ Wi, const float* __restrict__ Wf,
                            const float* __restrict__ Wog, const float* __restrict__ Wc)
{
    size_t idx = (size_t)blockIdx.x * blockDim.x + threadIdx.x;
    if (idx >= (size_t)KE * G4) return;
    int n = (int)(idx % G4);
    int k = (int)(idx / G4);
    int g = n >> 9;
    int j = n & (HH - 1);
    const float* src = (g == 0) ? Wi : (g == 1) ? Wf : (g == 2) ? Wog : Wc;
    g_Wstack[idx] = __float2half_rn(src[(size_t)(k & (HH - 1)) * HH + j]);
}

// Ustack[1024][2560]: both K-halves hold fp16(U)
__global__ void prep_ustack(const float* __restrict__ Ui, const float* __restrict__ Uf,
                            const float* __restrict__ Uog, const float* __restrict__ Uc,
                            const float* __restrict__ Wd)
{
    size_t idx = (size_t)blockIdx.x * blockDim.x + threadIdx.x;
    if (idx >= (size_t)KE * N5) return;
    int n = (int)(idx % N5);
    int k = (int)(idx / N5);
    int g = n >> 9;
    int j = n & (HH - 1);
    const float* src = (g == 0) ? Ui : (g == 1) ? Uf : (g == 2) ? Uog : (g == 3) ? Uc : Wd;
    g_Ustack[idx] = __float2half_rn(src[(size_t)(k & (HH - 1)) * HH + j]);
}

__global__ void prep_bias(const float* __restrict__ bi, const float* __restrict__ bf,
                          const float* __restrict__ bog, const float* __restrict__ bc)
{
    int n = blockIdx.x * blockDim.x + threadIdx.x;
    if (n >= G4) return;
    int g = n >> 9, j = n & (HH - 1);
    const float* src = (g == 0) ? bi : (g == 1) ? bf : (g == 2) ? bog : bc;
    g_bstack[n] = src[j];
}

// ---------------------------------------------------------------------------
// Precompute GEMM: g_gx[m][n] = Astack[m][:] @ Wstack[:][n] + bstack[n]
// M=131072, N=2048, K=1024.  CTA tile 128x128, 8 warps (4m x 2n), warp 32x64.
// Grid (16 n-blocks fast, 1024 m-blocks): B stays L2-resident.
// ---------------------------------------------------------------------------
__global__ void __launch_bounds__(256) gemm_pre()
{
    __shared__ __half As[2][128][40];
    __shared__ __half Bs[2][32][136];

    const int n0 = blockIdx.x * 128;
    const int m0 = blockIdx.y * 128;
    const int tid = threadIdx.x;
    const int warp = tid >> 5, lane = tid & 31;
    const int wm = warp & 3, wn = warp >> 2;

    const int lrow = (lane & 7) + ((lane >> 3) & 1) * 8;
    const int lcol = (lane >> 4) * 8;

    float acc[2][8][4];
    #pragma unroll
    for (int a = 0; a < 2; a++)
        #pragma unroll
        for (int b = 0; b < 8; b++)
            #pragma unroll
            for (int c = 0; c < 4; c++) acc[a][b][c] = 0.0f;

    auto load_stage = [&](int st, int kk) {
        const __half* aBase = (kk < 512) ? g_Axhi : g_Axlo;
        const int acolk = (kk & 511);
        #pragma unroll
        for (int r = 0; r < 2; r++) {
            int c  = tid + r * 256;
            int arow = c >> 2, ac8 = (c & 3) * 8;
            CP_ASYNC16(smem_u32(&As[st][arow][ac8]),
                       aBase + (size_t)(m0 + arow) * DD + acolk + ac8);
            int brow = c >> 4, bc8 = (c & 15) * 8;
            CP_ASYNC16(smem_u32(&Bs[st][brow][bc8]),
                       g_Wstack + (size_t)(kk + brow) * G4 + n0 + bc8);
        }
    };

    load_stage(0, 0);
    CP_COMMIT;

    for (int it = 0; it < NK; ++it) {
        if (it + 1 < NK) { load_stage((it + 1) & 1, (it + 1) * 32); CP_COMMIT; CP_WAIT1; }
        else            { CP_WAIT0; }
        __syncthreads();

        const int st = it & 1;
        #pragma unroll
        for (int kh = 0; kh < 2; kh++) {
            const int kb = kh * 16;
            unsigned afr[2][4], bfr[4][4];
            #pragma unroll
            for (int mt = 0; mt < 2; mt++)
                LDSM_X4(afr[mt], smem_u32(&As[st][wm * 32 + mt * 16 + lrow][kb + lcol]));
            #pragma unroll
            for (int nt = 0; nt < 4; nt++)
                LDSM_X4_T(bfr[nt], smem_u32(&Bs[st][kb + lrow][wn * 64 + nt * 16 + lcol]));
            #pragma unroll
            for (int mt = 0; mt < 2; mt++)
                #pragma unroll
                for (int nx = 0; nx < 8; nx++)
                    MMA_F16(acc[mt][nx], afr[mt], &bfr[nx >> 1][(nx & 1) * 2]);
        }
        __syncthreads();
    }

    const int qrow = lane >> 2, qcol = (lane & 3) * 2;
    #pragma unroll
    for (int mt = 0; mt < 2; mt++) {
        #pragma unroll
        for (int rr = 0; rr < 2; rr++) {
            int m = m0 + wm * 32 + mt * 16 + qrow + rr * 8;
            #pragma unroll
            for (int nx = 0; nx < 8; nx++) {
                int n = n0 + wn * 64 + nx * 8 + qcol;
                float2 bv = *(const float2*)&g_bstack[n];
                float2 v = make_float2(acc[mt][nx][rr * 2 + 0] + bv.x,
                                       acc[mt][nx][rr * 2 + 1] + bv.y);
                *(float2*)&g_gx[(size_t)m * G4 + n] = v;
            }
        }
    }
}

// ---------------------------------------------------------------------------
// Persistent TLSTM scan: 256 threads, split-K across warp pairs, KE=1024.
// ---------------------------------------------------------------------------
__global__ void __launch_bounds__(256, 1) tlstm_scan(
    const float* __restrict__ timep, const float* __restrict__ bd)
{
    extern __shared__ __half dyn[];
    float* red = (float*)dyn + RED_FOFF;

    const int m0 = blockIdx.x * 32;
    const int j0 = blockIdx.y * 32;
    const int tid = threadIdx.x;
    const int warp = tid >> 5, lane = tid & 31;
    const int wm = warp & 1, wj = (warp >> 1) & 1, wk = warp >> 2;

    const int lrow = (lane & 7) + ((lane >> 3) & 1) * 8;
    const int lcol = (lane >> 4) * 8;
    const int qrow = lane >> 2, qcol = (lane & 3) * 2;

    for (int t = 0; t < SS; ++t) {
        const int pp = t & 1;
        const __half* hhi = g_hhi[pp];
        const __half* hlo = g_hlo[pp];
        const __half* chi = g_chi[pp];
        const __half* clo = g_clo[pp];

        if (tid < 128) {
            int rr = tid & 31, gg = tid >> 5;
            const float* p = g_gx + ((size_t)t * BB + m0 + rr) * G4 + gg * HH + j0;
            asm volatile("prefetch.global.L2 [%0];" :: "l"(p));
            if (tid < 32) {
                const float* pc = g_c[pp] + (size_t)(m0 + tid) * HH + j0;
                asm volatile("prefetch.global.L2 [%0];" :: "l"(pc));
            }
        }

        auto load_stage = [&](int st, int kk) {
            const int pk = (kk & 511);
            if (tid < 128) {
                const __half* hB = (kk < 512) ? hhi : hlo;
                int row = tid >> 2, c8 = (tid & 3) * 8;
                CP_ASYNC16(smem_u32(&dyn[HS_OFF + (st * 32 + row) * PAD + c8]),
                           hB + (size_t)(m0 + row) * HH + pk + c8);
                const __half* ub = g_Ustack + (size_t)(kk + row) * N5 + j0 + c8;
                CP_ASYNC16(smem_u32(&dyn[BS_OFF + ((st * 5 + 0) * 32 + row) * PAD + c8]), ub + 0 * HH);
                CP_ASYNC16(smem_u32(&dyn[BS_OFF + ((st * 5 + 2) * 32 + row) * PAD + c8]), ub + 2 * HH);
                CP_ASYNC16(smem_u32(&dyn[BS_OFF + ((st * 5 + 4) * 32 + row) * PAD + c8]), ub + 4 * HH);
            } else {
                const __half* cB = (kk < 512) ? chi : clo;
                int u = tid - 128;
                int row = u >> 2, c8 = (u & 3) * 8;
                CP_ASYNC16(smem_u32(&dyn[CS_OFF + (st * 32 + row) * PAD + c8]),
                           cB + (size_t)(m0 + row) * HH + pk + c8);
                const __half* ub = g_Ustack + (size_t)(kk + row) * N5 + j0 + c8;
                CP_ASYNC16(smem_u32(&dyn[BS_OFF + ((st * 5 + 1) * 32 + row) * PAD + c8]), ub + 1 * HH);
                CP_ASYNC16(smem_u32(&dyn[BS_OFF + ((st * 5 + 3) * 32 + row) * PAD + c8]), ub + 3 * HH);
            }
        };

        float accG[4][2][4];
        float accD[2][4];
        #pragma unroll
        for (int g = 0; g < 4; g++)
            #pragma unroll
            for (int n = 0; n < 2; n++)
                #pragma unroll
                for (int c = 0; c < 4; c++) accG[g][n][c] = 0.0f;
        #pragma unroll
        for (int n = 0; n < 2; n++)
            #pragma unroll
            for (int c = 0; c < 4; c++) accD[n][c] = 0.0f;

        load_stage(0, 0);  CP_COMMIT;
        load_stage(1, 32); CP_COMMIT;

        const int kb = wk * 16;
        int stC = 0, stL = 2;
        for (int it = 0; it < NK; ++it) {
            CP_WAIT1;
            __syncthreads();
            const int ld = it + 2;
            if (ld < NK) load_stage(stL, ld * 32);
            CP_COMMIT;

            unsigned ah[4], ac[4], bf[5][4];
            LDSM_X4(ah, smem_u32(&dyn[HS_OFF + (stC * 32 + wm * 16 + lrow) * PAD + kb + lcol]));
            LDSM_X4(ac, smem_u32(&dyn[CS_OFF + (stC * 32 + wm * 16 + lrow) * PAD + kb + lcol]));
            #pragma unroll
            for (int g = 0; g < 5; g++)
                LDSM_X4_T(bf[g],
                    smem_u32(&dyn[BS_OFF + ((stC * 5 + g) * 32 + kb + lrow) * PAD + wj * 16 + lcol]));

            #pragma unroll
            for (int g = 0; g < 4; g++) {
                MMA_F16(accG[g][0], ah, &bf[g][0]);
                MMA_F16(accG[g][1], ah, &bf[g][2]);
            }
            MMA_F16(accD[0], ac, &bf[4][0]);
            MMA_F16(accD[1], ac, &bf[4][2]);

            stC = (stC == 2) ? 0 : stC + 1;
            stL = (stL == 2) ? 0 : stL + 1;
        }

        // ---- cross-pair reduction: ship the half we don't own ----
        {
            const int co = (1 - wk) * 2;
            float* myw = &red[(warp * 32 + lane) * 21];
            #pragma unroll
            for (int g = 0; g < 4; g++)
                #pragma unroll
                for (int n = 0; n < 2; n++) {
                    myw[g * 4 + n * 2 + 0] = accG[g][n][co + 0];
                    myw[g * 4 + n * 2 + 1] = accG[g][n][co + 1];
                }
            #pragma unroll
            for (int n = 0; n < 2; n++) {
                myw[16 + n * 2 + 0] = accD[n][co + 0];
                myw[16 + n * 2 + 1] = accD[n][co + 1];
            }
        }
        __syncthreads();
        const int c0 = wk * 2;
        {
            const float* pr = &red[((warp ^ 4) * 32 + lane) * 21];
            #pragma unroll
            for (int g = 0; g < 4; g++)
                #pragma unroll
                for (int n = 0; n < 2; n++) {
                    accG[g][n][c0 + 0] += pr[g * 4 + n * 2 + 0];
                    accG[g][n][c0 + 1] += pr[g * 4 + n * 2 + 1];
                }
            #pragma unroll
            for (int n = 0; n < 2; n++) {
                accD[n][c0 + 0] += pr[16 + n * 2 + 0];
                accD[n][c0 + 1] += pr[16 + n * 2 + 1];
            }
        }

        // ---------------- elementwise TLSTM update (rr = wk) ----------------
        const float* c_in  = g_c[pp];
        float*       h_out = g_h[pp ^ 1];
        float*       c_out = g_c[pp ^ 1];
        __half* hhi_o = g_hhi[pp ^ 1];
        __half* hlo_o = g_hlo[pp ^ 1];
        __half* chi_o = g_chi[pp ^ 1];
        __half* clo_o = g_clo[pp ^ 1];

        {
            const int m  = m0 + wm * 16 + wk * 8 + qrow;
            const float tv = timep[(size_t)m * SS + t];
            const float Tf = 1.0f / logf(tv + 2.7183f);
            const float* gxrow = g_gx + ((size_t)t * BB + m) * G4;
            #pragma unroll
            for (int n8 = 0; n8 < 2; n8++) {
                const int j = j0 + wj * 16 + n8 * 8 + qcol;
                const float2 gxi = *(const float2*)&gxrow[0 * HH + j];
                const float2 gxf = *(const float2*)&gxrow[1 * HH + j];
                const float2 gxo = *(const float2*)&gxrow[2 * HH + j];
                const float2 gxc = *(const float2*)&gxrow[3 * HH + j];
                const float2 cp  = *(const float2*)&c_in[(size_t)m * HH + j];
                const float2 bdv = *(const float2*)&bd[j];

                float d0 = accD[n8][c0 + 0], d1 = accD[n8][c0 + 1];
                float cst0 = tanhf(d0 + bdv.x), cst1 = tanhf(d1 + bdv.y);
                float c10 = cp.x - cst0 + Tf * cst0;
                float c11 = cp.y - cst1 + Tf * cst1;

                float i0 = sigf(accG[0][n8][c0 + 0] + gxi.x);
                float i1 = sigf(accG[0][n8][c0 + 1] + gxi.y);
                float f0 = sigf(accG[1][n8][c0 + 0] + gxf.x);
                float f1 = sigf(accG[1][n8][c0 + 1] + gxf.y);
                float o0 = sigf(accG[2][n8][c0 + 0] + gxo.x);
                float o1 = sigf(accG[2][n8][c0 + 1] + gxo.y);
                float n0v = tanhf(accG[3][n8][c0 + 0] + gxc.x);
                float n1v = tanhf(accG[3][n8][c0 + 1] + gxc.y);

                float cn0 = f0 * c10 + i0 * n0v;
                float cn1 = f1 * c11 + i1 * n1v;
                float hn0 = o0 * tanhf(cn0);
                float hn1 = o1 * tanhf(cn1);

                size_t off = (size_t)m * HH + j;
                *(float2*)&c_out[off] = make_float2(cn0, cn1);
                *(float2*)&h_out[off] = make_float2(hn0, hn1);

                __half ch0 = __float2half_rn(cn0), ch1 = __float2half_rn(cn1);
                __half hh0 = __float2half_rn(hn0), hh1 = __float2half_rn(hn1);
                *(__half2*)&chi_o[off] = __halves2half2(ch0, ch1);
                *(__half2*)&clo_o[off] = __halves2half2(
                    __float2half_rn(cn0 - __half2float(ch0)),
                    __float2half_rn(cn1 - __half2float(ch1)));
                *(__half2*)&hhi_o[off] = __halves2half2(hh0, hh1);
                *(__half2*)&hlo_o[off] = __halves2half2(
                    __float2half_rn(hn0 - __half2float(hh0)),
                    __float2half_rn(hn1 - __half2float(hh1)));
            }
        }

        grid_bar(t);
    }
}

// ---------------------------------------------------------------------------
__global__ void head_kernel(const float* __restrict__ Wo, const float* __restrict__ bo,
                            const float* __restrict__ Ws, const float* __restrict__ bs,
                            float* __restrict__ out)
{
    __shared__ float hrow[HH];
    __shared__ float fc[FCC];
    const int b = blockIdx.x;
    const float* h = g_h[0] + (size_t)b * HH;
    for (int k = threadIdx.x; k < HH; k += blockDim.x) hrow[k] = h[k];
    __syncthreads();

    const int j = threadIdx.x;
    float s = bo[j];
    for (int k = 0; k < HH; k++) s += hrow[k] * Wo[(size_t)k * FCC + j];
    fc[j] = fmaxf(s, 0.0f);
    __syncthreads();

    if (j < OO) {
        float r = bs[j];
        for (int q = 0; q < FCC; q++) r += fc[q] * Ws[(size_t)q * OO + j];
        out[(size_t)b * OO + j] = r;
    }
}

// ---------------------------------------------------------------------------
extern "C" void kernel_launch(void* const* d_in, const int* in_sizes, int n_in,
                              void* d_out, int out_size)
{
    const float* x   = (const float*)d_in[0];
    const float* tmv = (const float*)d_in[1];
    const float* Wi  = (const float*)d_in[2];
    const float* Ui  = (const float*)d_in[3];
    const float* bi  = (const float*)d_in[4];
    const float* Wf  = (const float*)d_in[5];
    const float* Uf  = (const float*)d_in[6];
    const float* bf  = (const float*)d_in[7];
    const float* Wog = (const float*)d_in[8];
    const float* Uog = (const float*)d_in[9];
    const float* bog = (const float*)d_in[10];
    const float* Wc  = (const float*)d_in[11];
    const float* Uc  = (const float*)d_in[12];
    const float* bc  = (const float*)d_in[13];
    const float* Wd  = (const float*)d_in[14];
    const float* bd  = (const float*)d_in[15];
    const float* Wo  = (const float*)d_in[16];
    const float* bo  = (const float*)d_in[17];
    const float* Ws  = (const float*)d_in[18];
    const float* bs  = (const float*)d_in[19];
    float* out = (float*)d_out;

    static bool attr_done = false;
    if (!attr_done) {
        cudaFuncSetAttribute(tlstm_scan,
                             cudaFuncAttributeMaxDynamicSharedMemorySize,
                             SCAN_SMEM_BYTES);
        attr_done = true;
    }

    init_state<<<(BB * HH + 255) / 256, 256>>>();

    {   size_t n = (size_t)SS * BB * DD;
        convert_x<<<(unsigned)((n + 255) / 256), 256>>>(x); }
    {   size_t n = (size_t)KE * G4;
        prep_wstack<<<(unsigned)((n + 255) / 256), 256>>>(Wi, Wf, Wog, Wc); }
    {   size_t n = (size_t)KE * N5;
        prep_ustack<<<(unsigned)((n + 255) / 256), 256>>>(Ui, Uf, Uog, Uc, Wd); }
    prep_bias<<<(G4 + 255) / 256, 256>>>(bi, bf, bog, bc);

    dim3 gg(16, 1024);      // x = n-blocks fast -> B L2-resident
    gemm_pre<<<gg, 256>>>();

    dim3 gs(8, 16);
    tlstm_scan<<<gs, 256, SCAN_SMEM_BYTES>>>(tmv, bd);

    head_kernel<<<BB, FCC>>>(Wo, bo, Ws, bs, out);
}

// round 10
// speedup vs baseline: 3.4492x; 1.2266x over previous
#include <cuda_runtime.h>
#include <cuda_fp16.h>
#include <math.h>
#include <stdint.h>

#define BB   256
#define SS   512
#define DD   512
#define HH   512
#define FCC  64
#define OO   2
#define G4   2048          // 4*H
#define KP   512           // gemm_pre K (single-plane x vs fp16 W)
#define NKP  16            // KP / 32
#define N5   2560          // 5*H
#define NK1  16            // scan phase-1 iters (K=512: hhi,chi vs U,Wd)
#define NK2  16            // scan phase-2 iters (K=512: clo vs Wd)
#define NKT  32            // total scan iters
#define NCTA 128           // scan grid (8 x 16)

// ---- scan kernel dynamic smem layout (fp16 elements), row pad 40 ----
#define PAD      40
#define HS_OFF   0
#define CS_OFF   (3 * 32 * PAD)
#define BS_OFF   (2 * 3 * 32 * PAD)
#define STAGE_ELEMS (2 * 3 * 32 * PAD + 3 * 5 * 32 * PAD)
#define RED_FOFF  (STAGE_ELEMS / 2)
#define RED_FLOATS (8 * 32 * 21)
#define SCAN_SMEM_BYTES (STAGE_ELEMS * 2 + RED_FLOATS * 4)

// ---------------------------------------------------------------------------
// Static device scratch (allocation-free contract)
// ---------------------------------------------------------------------------
__device__ float   g_gx[(size_t)SS * BB * G4];
__device__ __half  g_Axhi[(size_t)SS * BB * DD];   // fp16(x), single plane
__device__ __half  g_Wstack[(size_t)KP * G4];      // [512][2048] fp16(W)
__device__ __half  g_Ustack[(size_t)KP * N5];      // [512][2560] fp16(U | Wd)
__device__ float   g_bstack[G4];
__device__ float   g_h[2][BB * HH];
__device__ float   g_c[2][BB * HH];
__device__ __half  g_hhi[2][BB * HH];              // fp16(h), single plane
__device__ __half  g_chi[2][BB * HH];              // c hi/lo planes (decomp)
__device__ __half  g_clo[2][BB * HH];
__device__ unsigned g_count;

// ---------------------------------------------------------------------------
// PTX helpers
// ---------------------------------------------------------------------------
__device__ __forceinline__ unsigned smem_u32(const void* p)
{
    return (unsigned)__cvta_generic_to_shared(p);
}

#define CP_ASYNC16(dst_u32, src_ptr) \
    asm volatile("cp.async.cg.shared.global [%0],[%1],16;" :: "r"(dst_u32), "l"(src_ptr))
#define CP_COMMIT   asm volatile("cp.async.commit_group;")
#define CP_WAIT1    asm volatile("cp.async.wait_group 1;")
#define CP_WAIT0    asm volatile("cp.async.wait_group 0;")

#define LDSM_X4(r, addr) \
    asm volatile("ldmatrix.sync.aligned.m8n8.x4.shared.b16 {%0,%1,%2,%3},[%4];" \
                 : "=r"((r)[0]), "=r"((r)[1]), "=r"((r)[2]), "=r"((r)[3]) : "r"(addr))
#define LDSM_X4_T(r, addr) \
    asm volatile("ldmatrix.sync.aligned.m8n8.x4.trans.shared.b16 {%0,%1,%2,%3},[%4];" \
                 : "=r"((r)[0]), "=r"((r)[1]), "=r"((r)[2]), "=r"((r)[3]) : "r"(addr))

#define MMA_F16(d, a, b) \
    asm volatile("mma.sync.aligned.m16n8k16.row.col.f32.f16.f16.f32 " \
                 "{%0,%1,%2,%3},{%4,%5,%6,%7},{%8,%9},{%0,%1,%2,%3};" \
                 : "+f"((d)[0]), "+f"((d)[1]), "+f"((d)[2]), "+f"((d)[3]) \
                 : "r"((a)[0]), "r"((a)[1]), "r"((a)[2]), "r"((a)[3]), \
                   "r"((b)[0]), "r"((b)[1]))

__device__ __forceinline__ float sigf(float x) { return 1.0f / (1.0f + expf(-x)); }

__device__ __forceinline__ unsigned ld_acq_u32(const unsigned* p)
{
    unsigned v;
    asm volatile("ld.acquire.gpu.global.b32 %0,[%1];" : "=r"(v) : "l"(p) : "memory");
    return v;
}

__device__ __forceinline__ void grid_bar(int t)
{
    __threadfence();
    __syncthreads();
    if (threadIdx.x == 0) {
        atomicAdd(&g_count, 1u);
        const unsigned target = (unsigned)NCTA * (unsigned)(t + 1);
        while (ld_acq_u32(&g_count) < target) {
            __nanosleep(32);
        }
    }
    __syncthreads();
}

// ---------------------------------------------------------------------------
// Prep kernels
// ---------------------------------------------------------------------------
__global__ void init_state()
{
    int i = blockIdx.x * blockDim.x + threadIdx.x;
    if (i == 0) g_count = 0u;
    if (i < BB * HH) {
        g_h[0][i] = 0.0f;  g_c[0][i] = 0.0f;
        __half z = __float2half_rn(0.0f);
        g_hhi[0][i] = z; g_chi[0][i] = z; g_clo[0][i] = z;
    }
}

// x[b][t][k] -> fp16 plane at [(t*B+b)][k]
__global__ void convert_x(const float* __restrict__ x)
{
    size_t idx = (size_t)blockIdx.x * blockDim.x + threadIdx.x;
    if (idx >= (size_t)SS * BB * DD) return;
    int k = (int)(idx & (DD - 1));
    int m = (int)(idx >> 9);
    int b = m & (BB - 1);
    int t = m >> 8;
    g_Axhi[idx] = __float2half_rn(x[((size_t)b * SS + t) * DD + k]);
}

// Wstack[512][2048] = fp16(W)
__global__ void prep_wstack(const float* __restrict__ Wi, const float* __restrict__ Wf,
                            const float* __restrict__ Wog, const float* __restrict__ Wc)
{
    size_t idx = (size_t)blockIdx.x * blockDim.x + threadIdx.x;
    if (idx >= (size_t)KP * G4) return;
    int n = (int)(idx % G4);
    int k = (int)(idx / G4);
    int g = n >> 9;
    int j = n & (HH - 1);
    const float* src = (g == 0) ? Wi : (g == 1) ? Wf : (g == 2) ? Wog : Wc;
    g_Wstack[idx] = __float2half_rn(src[(size_t)k * HH + j]);
}

// Ustack[512][2560] = fp16(U gates | Wd)
__global__ void prep_ustack(const float* __restrict__ Ui, const float* __restrict__ Uf,
                            const float* __restrict__ Uog, const float* __restrict__ Uc,
                            const float* __restrict__ Wd)
{
    size_t idx = (size_t)blockIdx.x * blockDim.x + threadIdx.x;
    if (idx >= (size_t)KP * N5) return;
    int n = (int)(idx % N5);
    int k = (int)(idx / N5);
    int g = n >> 9;
    int j = n & (HH - 1);
    const float* src = (g == 0) ? Ui : (g == 1) ? Uf : (g == 2) ? Uog : (g == 3) ? Uc : Wd;
    g_Ustack[idx] = __float2half_rn(src[(size_t)k * HH + j]);
}

__global__ void prep_bias(const float* __restrict__ bi, const float* __restrict__ bf,
                          const float* __restrict__ bog, const float* __restrict__ bc)
{
    int n = blockIdx.x * blockDim.x + threadIdx.x;
    if (n >= G4) return;
    int g = n >> 9, j = n & (HH - 1);
    const float* src = (g == 0) ? bi : (g == 1) ? bf : (g == 2) ? bog : bc;
    g_bstack[n] = src[j];
}

// ---------------------------------------------------------------------------
// Precompute GEMM: g_gx[m][n] = x_f16[m][:] @ Wstack[:][n] + bstack[n]
// M=131072, N=2048, K=512.  CTA tile 128x128, 8 warps (4m x 2n), warp 32x64.
// Grid (16 n-blocks fast, 1024 m-blocks): B stays L2-resident.
// ---------------------------------------------------------------------------
__global__ void __launch_bounds__(256) gemm_pre()
{
    __shared__ __half As[2][128][40];
    __shared__ __half Bs[2][32][136];

    const int n0 = blockIdx.x * 128;
    const int m0 = blockIdx.y * 128;
    const int tid = threadIdx.x;
    const int warp = tid >> 5, lane = tid & 31;
    const int wm = warp & 3, wn = warp >> 2;

    const int lrow = (lane & 7) + ((lane >> 3) & 1) * 8;
    const int lcol = (lane >> 4) * 8;

    float acc[2][8][4];
    #pragma unroll
    for (int a = 0; a < 2; a++)
        #pragma unroll
        for (int b = 0; b < 8; b++)
            #pragma unroll
            for (int c = 0; c < 4; c++) acc[a][b][c] = 0.0f;

    auto load_stage = [&](int st, int kk) {
        #pragma unroll
        for (int r = 0; r < 2; r++) {
            int c  = tid + r * 256;
            int arow = c >> 2, ac8 = (c & 3) * 8;
            CP_ASYNC16(smem_u32(&As[st][arow][ac8]),
                       g_Axhi + (size_t)(m0 + arow) * DD + kk + ac8);
            int brow = c >> 4, bc8 = (c & 15) * 8;
            CP_ASYNC16(smem_u32(&Bs[st][brow][bc8]),
                       g_Wstack + (size_t)(kk + brow) * G4 + n0 + bc8);
        }
    };

    load_stage(0, 0);
    CP_COMMIT;

    for (int it = 0; it < NKP; ++it) {
        if (it + 1 < NKP) { load_stage((it + 1) & 1, (it + 1) * 32); CP_COMMIT; CP_WAIT1; }
        else             { CP_WAIT0; }
        __syncthreads();

        const int st = it & 1;
        #pragma unroll
        for (int kh = 0; kh < 2; kh++) {
            const int kb = kh * 16;
            unsigned afr[2][4], bfr[4][4];
            #pragma unroll
            for (int mt = 0; mt < 2; mt++)
                LDSM_X4(afr[mt], smem_u32(&As[st][wm * 32 + mt * 16 + lrow][kb + lcol]));
            #pragma unroll
            for (int nt = 0; nt < 4; nt++)
                LDSM_X4_T(bfr[nt], smem_u32(&Bs[st][kb + lrow][wn * 64 + nt * 16 + lcol]));
            #pragma unroll
            for (int mt = 0; mt < 2; mt++)
                #pragma unroll
                for (int nx = 0; nx < 8; nx++)
                    MMA_F16(acc[mt][nx], afr[mt], &bfr[nx >> 1][(nx & 1) * 2]);
        }
        __syncthreads();
    }

    const int qrow = lane >> 2, qcol = (lane & 3) * 2;
    #pragma unroll
    for (int mt = 0; mt < 2; mt++) {
        #pragma unroll
        for (int rr = 0; rr < 2; rr++) {
            int m = m0 + wm * 32 + mt * 16 + qrow + rr * 8;
            #pragma unroll
            for (int nx = 0; nx < 8; nx++) {
                int n = n0 + wn * 64 + nx * 8 + qcol;
                float2 bv = *(const float2*)&g_bstack[n];
                float2 v = make_float2(acc[mt][nx][rr * 2 + 0] + bv.x,
                                       acc[mt][nx][rr * 2 + 1] + bv.y);
                *(float2*)&g_gx[(size_t)m * G4 + n] = v;
            }
        }
    }
}

// ---------------------------------------------------------------------------
// Persistent TLSTM scan: 256 threads, split-K across warp pairs.
// Phase 1 (it 0..15, K=512): hhi vs {Ui,Uf,Uog,Uc}, chi vs Wd  (10 MMA/warp/iter)
// Phase 2 (it 16..31, K=512): clo vs Wd only                   (2 MMA/warp/iter)
// ---------------------------------------------------------------------------
__global__ void __launch_bounds__(256, 1) tlstm_scan(
    const float* __restrict__ timep, const float* __restrict__ bd)
{
    extern __shared__ __half dyn[];
    float* red = (float*)dyn + RED_FOFF;

    const int m0 = blockIdx.x * 32;
    const int j0 = blockIdx.y * 32;
    const int tid = threadIdx.x;
    const int warp = tid >> 5, lane = tid & 31;
    const int wm = warp & 1, wj = (warp >> 1) & 1, wk = warp >> 2;

    const int lrow = (lane & 7) + ((lane >> 3) & 1) * 8;
    const int lcol = (lane >> 4) * 8;
    const int qrow = lane >> 2, qcol = (lane & 3) * 2;

    for (int t = 0; t < SS; ++t) {
        const int pp = t & 1;
        const __half* hhi = g_hhi[pp];
        const __half* chi = g_chi[pp];
        const __half* clo = g_clo[pp];

        // L2 prefetch of epilogue operands
        if (tid < 128) {
            int rr = tid & 31, gg = tid >> 5;
            const float* p = g_gx + ((size_t)t * BB + m0 + rr) * G4 + gg * HH + j0;
            asm volatile("prefetch.global.L2 [%0];" :: "l"(p));
            if (tid < 32) {
                const float* pc = g_c[pp] + (size_t)(m0 + tid) * HH + j0;
                asm volatile("prefetch.global.L2 [%0];" :: "l"(pc));
            }
        }

        // itx < NK1: phase-1 stage (7 tiles). itx >= NK1: phase-2 stage (2 tiles).
        auto load_stage = [&](int st, int itx) {
            if (itx < NK1) {
                const int kk = itx * 32;
                if (tid < 128) {
                    int row = tid >> 2, c8 = (tid & 3) * 8;
                    CP_ASYNC16(smem_u32(&dyn[HS_OFF + (st * 32 + row) * PAD + c8]),
                               hhi + (size_t)(m0 + row) * HH + kk + c8);
                    const __half* ub = g_Ustack + (size_t)(kk + row) * N5 + j0 + c8;
                    CP_ASYNC16(smem_u32(&dyn[BS_OFF + ((st * 5 + 0) * 32 + row) * PAD + c8]), ub + 0 * HH);
                    CP_ASYNC16(smem_u32(&dyn[BS_OFF + ((st * 5 + 2) * 32 + row) * PAD + c8]), ub + 2 * HH);
                    CP_ASYNC16(smem_u32(&dyn[BS_OFF + ((st * 5 + 4) * 32 + row) * PAD + c8]), ub + 4 * HH);
                } else {
                    int u = tid - 128;
                    int row = u >> 2, c8 = (u & 3) * 8;
                    CP_ASYNC16(smem_u32(&dyn[CS_OFF + (st * 32 + row) * PAD + c8]),
                               chi + (size_t)(m0 + row) * HH + kk + c8);
                    const __half* ub = g_Ustack + (size_t)(kk + row) * N5 + j0 + c8;
                    CP_ASYNC16(smem_u32(&dyn[BS_OFF + ((st * 5 + 1) * 32 + row) * PAD + c8]), ub + 1 * HH);
                    CP_ASYNC16(smem_u32(&dyn[BS_OFF + ((st * 5 + 3) * 32 + row) * PAD + c8]), ub + 3 * HH);
                }
            } else {
                const int kk = (itx - NK1) * 32;
                if (tid < 128) {
                    int row = tid >> 2, c8 = (tid & 3) * 8;
                    CP_ASYNC16(smem_u32(&dyn[CS_OFF + (st * 32 + row) * PAD + c8]),
                               clo + (size_t)(m0 + row) * HH + kk + c8);
                } else {
                    int u = tid - 128;
                    int row = u >> 2, c8 = (u & 3) * 8;
                    CP_ASYNC16(smem_u32(&dyn[BS_OFF + ((st * 5 + 4) * 32 + row) * PAD + c8]),
                               g_Ustack + (size_t)(kk + row) * N5 + 4 * HH + j0 + c8);
                }
            }
        };

        float accG[4][2][4];
        float accD[2][4];
        #pragma unroll
        for (int g = 0; g < 4; g++)
            #pragma unroll
            for (int n = 0; n < 2; n++)
                #pragma unroll
                for (int c = 0; c < 4; c++) accG[g][n][c] = 0.0f;
        #pragma unroll
        for (int n = 0; n < 2; n++)
            #pragma unroll
            for (int c = 0; c < 4; c++) accD[n][c] = 0.0f;

        load_stage(0, 0);  CP_COMMIT;
        load_stage(1, 1);  CP_COMMIT;

        const int kb = wk * 16;
        int stC = 0, stL = 2;
        for (int it = 0; it < NKT; ++it) {
            CP_WAIT1;
            __syncthreads();
            if (it + 2 < NKT) load_stage(stL, it + 2);
            CP_COMMIT;

            if (it < NK1) {
                unsigned ah[4], ac[4], bf[5][4];
                LDSM_X4(ah, smem_u32(&dyn[HS_OFF + (stC * 32 + wm * 16 + lrow) * PAD + kb + lcol]));
                LDSM_X4(ac, smem_u32(&dyn[CS_OFF + (stC * 32 + wm * 16 + lrow) * PAD + kb + lcol]));
                #pragma unroll
                for (int g = 0; g < 5; g++)
                    LDSM_X4_T(bf[g],
                        smem_u32(&dyn[BS_OFF + ((stC * 5 + g) * 32 + kb + lrow) * PAD + wj * 16 + lcol]));

                #pragma unroll
                for (int g = 0; g < 4; g++) {
                    MMA_F16(accG[g][0], ah, &bf[g][0]);
                    MMA_F16(accG[g][1], ah, &bf[g][2]);
                }
                MMA_F16(accD[0], ac, &bf[4][0]);
                MMA_F16(accD[1], ac, &bf[4][2]);
            } else {
                unsigned ac[4], bf4[4];
                LDSM_X4(ac, smem_u32(&dyn[CS_OFF + (stC * 32 + wm * 16 + lrow) * PAD + kb + lcol]));
                LDSM_X4_T(bf4,
                    smem_u32(&dyn[BS_OFF + ((stC * 5 + 4) * 32 + kb + lrow) * PAD + wj * 16 + lcol]));
                MMA_F16(accD[0], ac, &bf4[0]);
                MMA_F16(accD[1], ac, &bf4[2]);
            }

            stC = (stC == 2) ? 0 : stC + 1;
            stL = (stL == 2) ? 0 : stL + 1;
        }

        // ---- cross-pair reduction: ship the half we don't own ----
        {
            const int co = (1 - wk) * 2;
            float* myw = &red[(warp * 32 + lane) * 21];
            #pragma unroll
            for (int g = 0; g < 4; g++)
                #pragma unroll
                for (int n = 0; n < 2; n++) {
                    myw[g * 4 + n * 2 + 0] = accG[g][n][co + 0];
                    myw[g * 4 + n * 2 + 1] = accG[g][n][co + 1];
                }
            #pragma unroll
            for (int n = 0; n < 2; n++) {
                myw[16 + n * 2 + 0] = accD[n][co + 0];
                myw[16 + n * 2 + 1] = accD[n][co + 1];
            }
        }
        __syncthreads();
        const int c0 = wk * 2;
        {
            const float* pr = &red[((warp ^ 4) * 32 + lane) * 21];
            #pragma unroll
            for (int g = 0; g < 4; g++)
                #pragma unroll
                for (int n = 0; n < 2; n++) {
                    accG[g][n][c0 + 0] += pr[g * 4 + n * 2 + 0];
                    accG[g][n][c0 + 1] += pr[g * 4 + n * 2 + 1];
                }
            #pragma unroll
            for (int n = 0; n < 2; n++) {
                accD[n][c0 + 0] += pr[16 + n * 2 + 0];
                accD[n][c0 + 1] += pr[16 + n * 2 + 1];
            }
        }

        // ---------------- elementwise TLSTM update (row group = wk) ---------
        const float* c_in  = g_c[pp];
        float*       h_out = g_h[pp ^ 1];
        float*       c_out = g_c[pp ^ 1];
        __half* hhi_o = g_hhi[pp ^ 1];
        __half* chi_o = g_chi[pp ^ 1];
        __half* clo_o = g_clo[pp ^ 1];

        {
            const int m  = m0 + wm * 16 + wk * 8 + qrow;
            const float tv = timep[(size_t)m * SS + t];
            const float Tf = 1.0f / logf(tv + 2.7183f);
            const float* gxrow = g_gx + ((size_t)t * BB + m) * G4;
            #pragma unroll
            for (int n8 = 0; n8 < 2; n8++) {
                const int j = j0 + wj * 16 + n8 * 8 + qcol;
                const float2 gxi = *(const float2*)&gxrow[0 * HH + j];
                const float2 gxf = *(const float2*)&gxrow[1 * HH + j];
                const float2 gxo = *(const float2*)&gxrow[2 * HH + j];
                const float2 gxc = *(const float2*)&gxrow[3 * HH + j];
                const float2 cp  = *(const float2*)&c_in[(size_t)m * HH + j];
                const float2 bdv = *(const float2*)&bd[j];

                float d0 = accD[n8][c0 + 0], d1 = accD[n8][c0 + 1];
                float cst0 = tanhf(d0 + bdv.x), cst1 = tanhf(d1 + bdv.y);
                float c10 = cp.x - cst0 + Tf * cst0;
                float c11 = cp.y - cst1 + Tf * cst1;

                float i0 = sigf(accG[0][n8][c0 + 0] + gxi.x);
                float i1 = sigf(accG[0][n8][c0 + 1] + gxi.y);
                float f0 = sigf(accG[1][n8][c0 + 0] + gxf.x);
                float f1 = sigf(accG[1][n8][c0 + 1] + gxf.y);
                float o0 = sigf(accG[2][n8][c0 + 0] + gxo.x);
                float o1 = sigf(accG[2][n8][c0 + 1] + gxo.y);
                float n0v = tanhf(accG[3][n8][c0 + 0] + gxc.x);
                float n1v = tanhf(accG[3][n8][c0 + 1] + gxc.y);

                float cn0 = f0 * c10 + i0 * n0v;
                float cn1 = f1 * c11 + i1 * n1v;
                float hn0 = o0 * tanhf(cn0);
                float hn1 = o1 * tanhf(cn1);

                size_t off = (size_t)m * HH + j;
                *(float2*)&c_out[off] = make_float2(cn0, cn1);
                *(float2*)&h_out[off] = make_float2(hn0, hn1);

                __half ch0 = __float2half_rn(cn0), ch1 = __float2half_rn(cn1);
                *(__half2*)&chi_o[off] = __halves2half2(ch0, ch1);
                *(__half2*)&clo_o[off] = __halves2half2(
                    __float2half_rn(cn0 - __half2float(ch0)),
                    __float2half_rn(cn1 - __half2float(ch1)));
                *(__half2*)&hhi_o[off] = __halves2half2(
                    __float2half_rn(hn0), __float2half_rn(hn1));
            }
        }

        grid_bar(t);
    }
}

// ---------------------------------------------------------------------------
__global__ void head_kernel(const float* __restrict__ Wo, const float* __restrict__ bo,
                            const float* __restrict__ Ws, const float* __restrict__ bs,
                            float* __restrict__ out)
{
    __shared__ float hrow[HH];
    __shared__ float fc[FCC];
    const int b = blockIdx.x;
    const float* h = g_h[0] + (size_t)b * HH;
    for (int k = threadIdx.x; k < HH; k += blockDim.x) hrow[k] = h[k];
    __syncthreads();

    const int j = threadIdx.x;
    float s = bo[j];
    for (int k = 0; k < HH; k++) s += hrow[k] * Wo[(size_t)k * FCC + j];
    fc[j] = fmaxf(s, 0.0f);
    __syncthreads();

    if (j < OO) {
        float r = bs[j];
        for (int q = 0; q < FCC; q++) r += fc[q] * Ws[(size_t)q * OO + j];
        out[(size_t)b * OO + j] = r;
    }
}

// ---------------------------------------------------------------------------
extern "C" void kernel_launch(void* const* d_in, const int* in_sizes, int n_in,
                              void* d_out, int out_size)
{
    const float* x   = (const float*)d_in[0];
    const float* tmv = (const float*)d_in[1];
    const float* Wi  = (const float*)d_in[2];
    const float* Ui  = (const float*)d_in[3];
    const float* bi  = (const float*)d_in[4];
    const float* Wf  = (const float*)d_in[5];
    const float* Uf  = (const float*)d_in[6];
    const float* bf  = (const float*)d_in[7];
    const float* Wog = (const float*)d_in[8];
    const float* Uog = (const float*)d_in[9];
    const float* bog = (const float*)d_in[10];
    const float* Wc  = (const float*)d_in[11];
    const float* Uc  = (const float*)d_in[12];
    const float* bc  = (const float*)d_in[13];
    const float* Wd  = (const float*)d_in[14];
    const float* bd  = (const float*)d_in[15];
    const float* Wo  = (const float*)d_in[16];
    const float* bo  = (const float*)d_in[17];
    const float* Ws  = (const float*)d_in[18];
    const float* bs  = (const float*)d_in[19];
    float* out = (float*)d_out;

    static bool attr_done = false;
    if (!attr_done) {
        cudaFuncSetAttribute(tlstm_scan,
                             cudaFuncAttributeMaxDynamicSharedMemorySize,
                             SCAN_SMEM_BYTES);
        attr_done = true;
    }

    init_state<<<(BB * HH + 255) / 256, 256>>>();

    {   size_t n = (size_t)SS * BB * DD;
        convert_x<<<(unsigned)((n + 255) / 256), 256>>>(x); }
    {   size_t n = (size_t)KP * G4;
        prep_wstack<<<(unsigned)((n + 255) / 256), 256>>>(Wi, Wf, Wog, Wc); }
    {   size_t n = (size_t)KP * N5;
        prep_ustack<<<(unsigned)((n + 255) / 256), 256>>>(Ui, Uf, Uog, Uc, Wd); }
    prep_bias<<<(G4 + 255) / 256, 256>>>(bi, bf, bog, bc);

    dim3 gg(16, 1024);      // x = n-blocks fast -> B L2-resident
    gemm_pre<<<gg, 256>>>();

    dim3 gs(8, 16);
    tlstm_scan<<<gs, 256, SCAN_SMEM_BYTES>>>(tmv, bd);

    head_kernel<<<BB, FCC>>>(Wo, bo, Ws, bs, out);
}

// round 11
// speedup vs baseline: 4.6103x; 1.3366x over previous
#include <cuda_runtime.h>
#include <cuda_fp16.h>
#include <math.h>
#include <stdint.h>

#define BB   256
#define SS   512
#define DD   512
#define HH   512
#define FCC  64
#define OO   2
#define G4   2048          // 4*H
#define KP   512           // gemm_pre K (single-plane x vs fp16 W)
#define NKP  16            // KP / 32
#define N5   2560          // 5*H
#define NKT  16            // scan iters (K=512, single-plane h and c)
#define NCTA 128           // scan grid (8 x 16)

// ---- scan kernel dynamic smem layout (fp16 elements), row pad 40 ----
#define PAD      40
#define HS_OFF   0
#define CS_OFF   (3 * 32 * PAD)
#define BS_OFF   (2 * 3 * 32 * PAD)
#define STAGE_ELEMS (2 * 3 * 32 * PAD + 3 * 5 * 32 * PAD)
#define RED_FOFF  (STAGE_ELEMS / 2)
#define RED_FLOATS (8 * 32 * 21)
#define SCAN_SMEM_BYTES (STAGE_ELEMS * 2 + RED_FLOATS * 4)

// ---------------------------------------------------------------------------
// Static device scratch (allocation-free contract)
// ---------------------------------------------------------------------------
__device__ float   g_gx[(size_t)SS * BB * G4];
__device__ __half  g_Axhi[(size_t)SS * BB * DD];   // fp16(x), single plane
__device__ __half  g_Wstack[(size_t)KP * G4];      // [512][2048] fp16(W)
__device__ __half  g_Ustack[(size_t)KP * N5];      // [512][2560] fp16(U | Wd)
__device__ float   g_bstack[G4];
__device__ float   g_h[2][BB * HH];
__device__ float   g_c[2][BB * HH];
__device__ __half  g_hhi[2][BB * HH];              // fp16(h), single plane
__device__ __half  g_chi[2][BB * HH];              // fp16(c), single plane
__device__ unsigned g_count;

// ---------------------------------------------------------------------------
// PTX helpers
// ---------------------------------------------------------------------------
__device__ __forceinline__ unsigned smem_u32(const void* p)
{
    return (unsigned)__cvta_generic_to_shared(p);
}

#define CP_ASYNC16(dst_u32, src_ptr) \
    asm volatile("cp.async.cg.shared.global [%0],[%1],16;" :: "r"(dst_u32), "l"(src_ptr))
#define CP_COMMIT   asm volatile("cp.async.commit_group;")
#define CP_WAIT1    asm volatile("cp.async.wait_group 1;")
#define CP_WAIT0    asm volatile("cp.async.wait_group 0;")

#define LDSM_X4(r, addr) \
    asm volatile("ldmatrix.sync.aligned.m8n8.x4.shared.b16 {%0,%1,%2,%3},[%4];" \
                 : "=r"((r)[0]), "=r"((r)[1]), "=r"((r)[2]), "=r"((r)[3]) : "r"(addr))
#define LDSM_X4_T(r, addr) \
    asm volatile("ldmatrix.sync.aligned.m8n8.x4.trans.shared.b16 {%0,%1,%2,%3},[%4];" \
                 : "=r"((r)[0]), "=r"((r)[1]), "=r"((r)[2]), "=r"((r)[3]) : "r"(addr))

#define MMA_F16(d, a, b) \
    asm volatile("mma.sync.aligned.m16n8k16.row.col.f32.f16.f16.f32 " \
                 "{%0,%1,%2,%3},{%4,%5,%6,%7},{%8,%9},{%0,%1,%2,%3};" \
                 : "+f"((d)[0]), "+f"((d)[1]), "+f"((d)[2]), "+f"((d)[3]) \
                 : "r"((a)[0]), "r"((a)[1]), "r"((a)[2]), "r"((a)[3]), \
                   "r"((b)[0]), "r"((b)[1]))

__device__ __forceinline__ float sigf(float x) { return 1.0f / (1.0f + expf(-x)); }

__device__ __forceinline__ unsigned ld_acq_u32(const unsigned* p)
{
    unsigned v;
    asm volatile("ld.acquire.gpu.global.b32 %0,[%1];" : "=r"(v) : "l"(p) : "memory");
    return v;
}

__device__ __forceinline__ void grid_bar(int t)
{
    __threadfence();
    __syncthreads();
    if (threadIdx.x == 0) {
        atomicAdd(&g_count, 1u);
        const unsigned target = (unsigned)NCTA * (unsigned)(t + 1);
        while (ld_acq_u32(&g_count) < target) {
            __nanosleep(32);
        }
    }
    __syncthreads();
}

// ---------------------------------------------------------------------------
// Prep kernels
// ---------------------------------------------------------------------------
__global__ void init_state()
{
    int i = blockIdx.x * blockDim.x + threadIdx.x;
    if (i == 0) g_count = 0u;
    if (i < BB * HH) {
        g_h[0][i] = 0.0f;  g_c[0][i] = 0.0f;
        __half z = __float2half_rn(0.0f);
        g_hhi[0][i] = z; g_chi[0][i] = z;
    }
}

// x[b][t][k] -> fp16 plane at [(t*B+b)][k]
__global__ void convert_x(const float* __restrict__ x)
{
    size_t idx = (size_t)blockIdx.x * blockDim.x + threadIdx.x;
    if (idx >= (size_t)SS * BB * DD) return;
    int k = (int)(idx & (DD - 1));
    int m = (int)(idx >> 9);
    int b = m & (BB - 1);
    int t = m >> 8;
    g_Axhi[idx] = __float2half_rn(x[((size_t)b * SS + t) * DD + k]);
}

// Wstack[512][2048] = fp16(W)
__global__ void prep_wstack(const float* __restrict__ Wi, const float* __restrict__ Wf,
                            const float* __restrict__ Wog, const float* __restrict__ Wc)
{
    size_t idx = (size_t)blockIdx.x * blockDim.x + threadIdx.x;
    if (idx >= (size_t)KP * G4) return;
    int n = (int)(idx % G4);
    int k = (int)(idx / G4);
    int g = n >> 9;
    int j = n & (HH - 1);
    const float* src = (g == 0) ? Wi : (g == 1) ? Wf : (g == 2) ? Wog : Wc;
    g_Wstack[idx] = __float2half_rn(src[(size_t)k * HH + j]);
}

// Ustack[512][2560] = fp16(U gates | Wd)
__global__ void prep_ustack(const float* __restrict__ Ui, const float* __restrict__ Uf,
                            const float* __restrict__ Uog, const float* __restrict__ Uc,
                            const float* __restrict__ Wd)
{
    size_t idx = (size_t)blockIdx.x * blockDim.x + threadIdx.x;
    if (idx >= (size_t)KP * N5) return;
    int n = (int)(idx % N5);
    int k = (int)(idx / N5);
    int g = n >> 9;
    int j = n & (HH - 1);
    const float* src = (g == 0) ? Ui : (g == 1) ? Uf : (g == 2) ? Uog : (g == 3) ? Uc : Wd;
    g_Ustack[idx] = __float2half_rn(src[(size_t)k * HH + j]);
}

__global__ void prep_bias(const float* __restrict__ bi, const float* __restrict__ bf,
                          const float* __restrict__ bog, const float* __restrict__ bc)
{
    int n = blockIdx.x * blockDim.x + threadIdx.x;
    if (n >= G4) return;
    int g = n >> 9, j = n & (HH - 1);
    const float* src = (g == 0) ? bi : (g == 1) ? bf : (g == 2) ? bog : bc;
    g_bstack[n] = src[j];
}

// ---------------------------------------------------------------------------
// Precompute GEMM: g_gx[m][n] = x_f16[m][:] @ Wstack[:][n] + bstack[n]
// M=131072, N=2048, K=512.  CTA tile 128x128, 8 warps (4m x 2n), warp 32x64.
// Grid (16 n-blocks fast, 1024 m-blocks): B stays L2-resident.
// ---------------------------------------------------------------------------
__global__ void __launch_bounds__(256) gemm_pre()
{
    __shared__ __half As[2][128][40];
    __shared__ __half Bs[2][32][136];

    const int n0 = blockIdx.x * 128;
    const int m0 = blockIdx.y * 128;
    const int tid = threadIdx.x;
    const int warp = tid >> 5, lane = tid & 31;
    const int wm = warp & 3, wn = warp >> 2;

    const int lrow = (lane & 7) + ((lane >> 3) & 1) * 8;
    const int lcol = (lane >> 4) * 8;

    float acc[2][8][4];
    #pragma unroll
    for (int a = 0; a < 2; a++)
        #pragma unroll
        for (int b = 0; b < 8; b++)
            #pragma unroll
            for (int c = 0; c < 4; c++) acc[a][b][c] = 0.0f;

    auto load_stage = [&](int st, int kk) {
        #pragma unroll
        for (int r = 0; r < 2; r++) {
            int c  = tid + r * 256;
            int arow = c >> 2, ac8 = (c & 3) * 8;
            CP_ASYNC16(smem_u32(&As[st][arow][ac8]),
                       g_Axhi + (size_t)(m0 + arow) * DD + kk + ac8);
            int brow = c >> 4, bc8 = (c & 15) * 8;
            CP_ASYNC16(smem_u32(&Bs[st][brow][bc8]),
                       g_Wstack + (size_t)(kk + brow) * G4 + n0 + bc8);
        }
    };

    load_stage(0, 0);
    CP_COMMIT;

    for (int it = 0; it < NKP; ++it) {
        if (it + 1 < NKP) { load_stage((it + 1) & 1, (it + 1) * 32); CP_COMMIT; CP_WAIT1; }
        else             { CP_WAIT0; }
        __syncthreads();

        const int st = it & 1;
        #pragma unroll
        for (int kh = 0; kh < 2; kh++) {
            const int kb = kh * 16;
            unsigned afr[2][4], bfr[4][4];
            #pragma unroll
            for (int mt = 0; mt < 2; mt++)
                LDSM_X4(afr[mt], smem_u32(&As[st][wm * 32 + mt * 16 + lrow][kb + lcol]));
            #pragma unroll
            for (int nt = 0; nt < 4; nt++)
                LDSM_X4_T(bfr[nt], smem_u32(&Bs[st][kb + lrow][wn * 64 + nt * 16 + lcol]));
            #pragma unroll
            for (int mt = 0; mt < 2; mt++)
                #pragma unroll
                for (int nx = 0; nx < 8; nx++)
                    MMA_F16(acc[mt][nx], afr[mt], &bfr[nx >> 1][(nx & 1) * 2]);
        }
        __syncthreads();
    }

    const int qrow = lane >> 2, qcol = (lane & 3) * 2;
    #pragma unroll
    for (int mt = 0; mt < 2; mt++) {
        #pragma unroll
        for (int rr = 0; rr < 2; rr++) {
            int m = m0 + wm * 32 + mt * 16 + qrow + rr * 8;
            #pragma unroll
            for (int nx = 0; nx < 8; nx++) {
                int n = n0 + wn * 64 + nx * 8 + qcol;
                float2 bv = *(const float2*)&g_bstack[n];
                float2 v = make_float2(acc[mt][nx][rr * 2 + 0] + bv.x,
                                       acc[mt][nx][rr * 2 + 1] + bv.y);
                *(float2*)&g_gx[(size_t)m * G4 + n] = v;
            }
        }
    }
}

// ---------------------------------------------------------------------------
// Persistent TLSTM scan: 256 threads, split-K across warp pairs, K=512.
// Single phase: 16 iters, hhi vs {Ui,Uf,Uog,Uc} + chi vs Wd (10 MMA/warp/iter).
// ---------------------------------------------------------------------------
__global__ void __launch_bounds__(256, 1) tlstm_scan(
    const float* __restrict__ timep, const float* __restrict__ bd)
{
    extern __shared__ __half dyn[];
    float* red = (float*)dyn + RED_FOFF;

    const int m0 = blockIdx.x * 32;
    const int j0 = blockIdx.y * 32;
    const int tid = threadIdx.x;
    const int warp = tid >> 5, lane = tid & 31;
    const int wm = warp & 1, wj = (warp >> 1) & 1, wk = warp >> 2;

    const int lrow = (lane & 7) + ((lane >> 3) & 1) * 8;
    const int lcol = (lane >> 4) * 8;
    const int qrow = lane >> 2, qcol = (lane & 3) * 2;

    for (int t = 0; t < SS; ++t) {
        const int pp = t & 1;
        const __half* hhi = g_hhi[pp];
        const __half* chi = g_chi[pp];

        // L2 prefetch of epilogue operands
        if (tid < 128) {
            int rr = tid & 31, gg = tid >> 5;
            const float* p = g_gx + ((size_t)t * BB + m0 + rr) * G4 + gg * HH + j0;
            asm volatile("prefetch.global.L2 [%0];" :: "l"(p));
            if (tid < 32) {
                const float* pc = g_c[pp] + (size_t)(m0 + tid) * HH + j0;
                asm volatile("prefetch.global.L2 [%0];" :: "l"(pc));
            }
        }

        auto load_stage = [&](int st, int itx) {
            const int kk = itx * 32;
            if (tid < 128) {
                int row = tid >> 2, c8 = (tid & 3) * 8;
                CP_ASYNC16(smem_u32(&dyn[HS_OFF + (st * 32 + row) * PAD + c8]),
                           hhi + (size_t)(m0 + row) * HH + kk + c8);
                const __half* ub = g_Ustack + (size_t)(kk + row) * N5 + j0 + c8;
                CP_ASYNC16(smem_u32(&dyn[BS_OFF + ((st * 5 + 0) * 32 + row) * PAD + c8]), ub + 0 * HH);
                CP_ASYNC16(smem_u32(&dyn[BS_OFF + ((st * 5 + 2) * 32 + row) * PAD + c8]), ub + 2 * HH);
                CP_ASYNC16(smem_u32(&dyn[BS_OFF + ((st * 5 + 4) * 32 + row) * PAD + c8]), ub + 4 * HH);
            } else {
                int u = tid - 128;
                int row = u >> 2, c8 = (u & 3) * 8;
                CP_ASYNC16(smem_u32(&dyn[CS_OFF + (st * 32 + row) * PAD + c8]),
                           chi + (size_t)(m0 + row) * HH + kk + c8);
                const __half* ub = g_Ustack + (size_t)(kk + row) * N5 + j0 + c8;
                CP_ASYNC16(smem_u32(&dyn[BS_OFF + ((st * 5 + 1) * 32 + row) * PAD + c8]), ub + 1 * HH);
                CP_ASYNC16(smem_u32(&dyn[BS_OFF + ((st * 5 + 3) * 32 + row) * PAD + c8]), ub + 3 * HH);
            }
        };

        float accG[4][2][4];
        float accD[2][4];
        #pragma unroll
        for (int g = 0; g < 4; g++)
            #pragma unroll
            for (int n = 0; n < 2; n++)
                #pragma unroll
                for (int c = 0; c < 4; c++) accG[g][n][c] = 0.0f;
        #pragma unroll
        for (int n = 0; n < 2; n++)
            #pragma unroll
            for (int c = 0; c < 4; c++) accD[n][c] = 0.0f;

        load_stage(0, 0);  CP_COMMIT;
        load_stage(1, 1);  CP_COMMIT;

        const int kb = wk * 16;
        int stC = 0, stL = 2;
        for (int it = 0; it < NKT; ++it) {
            CP_WAIT1;
            __syncthreads();
            if (it + 2 < NKT) load_stage(stL, it + 2);
            CP_COMMIT;

            unsigned ah[4], ac[4], bf[5][4];
            LDSM_X4(ah, smem_u32(&dyn[HS_OFF + (stC * 32 + wm * 16 + lrow) * PAD + kb + lcol]));
            LDSM_X4(ac, smem_u32(&dyn[CS_OFF + (stC * 32 + wm * 16 + lrow) * PAD + kb + lcol]));
            #pragma unroll
            for (int g = 0; g < 5; g++)
                LDSM_X4_T(bf[g],
                    smem_u32(&dyn[BS_OFF + ((stC * 5 + g) * 32 + kb + lrow) * PAD + wj * 16 + lcol]));

            #pragma unroll
            for (int g = 0; g < 4; g++) {
                MMA_F16(accG[g][0], ah, &bf[g][0]);
                MMA_F16(accG[g][1], ah, &bf[g][2]);
            }
            MMA_F16(accD[0], ac, &bf[4][0]);
            MMA_F16(accD[1], ac, &bf[4][2]);

            stC = (stC == 2) ? 0 : stC + 1;
            stL = (stL == 2) ? 0 : stL + 1;
        }

        // ---- cross-pair reduction: ship the half we don't own ----
        {
            const int co = (1 - wk) * 2;
            float* myw = &red[(warp * 32 + lane) * 21];
            #pragma unroll
            for (int g = 0; g < 4; g++)
                #pragma unroll
                for (int n = 0; n < 2; n++) {
                    myw[g * 4 + n * 2 + 0] = accG[g][n][co + 0];
                    myw[g * 4 + n * 2 + 1] = accG[g][n][co + 1];
                }
            #pragma unroll
            for (int n = 0; n < 2; n++) {
                myw[16 + n * 2 + 0] = accD[n][co + 0];
                myw[16 + n * 2 + 1] = accD[n][co + 1];
            }
        }
        __syncthreads();
        const int c0 = wk * 2;
        {
            const float* pr = &red[((warp ^ 4) * 32 + lane) * 21];
            #pragma unroll
            for (int g = 0; g < 4; g++)
                #pragma unroll
                for (int n = 0; n < 2; n++) {
                    accG[g][n][c0 + 0] += pr[g * 4 + n * 2 + 0];
                    accG[g][n][c0 + 1] += pr[g * 4 + n * 2 + 1];
                }
            #pragma unroll
            for (int n = 0; n < 2; n++) {
                accD[n][c0 + 0] += pr[16 + n * 2 + 0];
                accD[n][c0 + 1] += pr[16 + n * 2 + 1];
            }
        }

        // ---------------- elementwise TLSTM update (row group = wk) ---------
        const float* c_in  = g_c[pp];
        float*       h_out = g_h[pp ^ 1];
        float*       c_out = g_c[pp ^ 1];
        __half* hhi_o = g_hhi[pp ^ 1];
        __half* chi_o = g_chi[pp ^ 1];

        {
            const int m  = m0 + wm * 16 + wk * 8 + qrow;
            const float tv = timep[(size_t)m * SS + t];
            const float Tf = 1.0f / logf(tv + 2.7183f);
            const float* gxrow = g_gx + ((size_t)t * BB + m) * G4;
            #pragma unroll
            for (int n8 = 0; n8 < 2; n8++) {
                const int j = j0 + wj * 16 + n8 * 8 + qcol;
                const float2 gxi = *(const float2*)&gxrow[0 * HH + j];
                const float2 gxf = *(const float2*)&gxrow[1 * HH + j];
                const float2 gxo = *(const float2*)&gxrow[2 * HH + j];
                const float2 gxc = *(const float2*)&gxrow[3 * HH + j];
                const float2 cp  = *(const float2*)&c_in[(size_t)m * HH + j];
                const float2 bdv = *(const float2*)&bd[j];

                float d0 = accD[n8][c0 + 0], d1 = accD[n8][c0 + 1];
                float cst0 = tanhf(d0 + bdv.x), cst1 = tanhf(d1 + bdv.y);
                float c10 = cp.x - cst0 + Tf * cst0;
                float c11 = cp.y - cst1 + Tf * cst1;

                float i0 = sigf(accG[0][n8][c0 + 0] + gxi.x);
                float i1 = sigf(accG[0][n8][c0 + 1] + gxi.y);
                float f0 = sigf(accG[1][n8][c0 + 0] + gxf.x);
                float f1 = sigf(accG[1][n8][c0 + 1] + gxf.y);
                float o0 = sigf(accG[2][n8][c0 + 0] + gxo.x);
                float o1 = sigf(accG[2][n8][c0 + 1] + gxo.y);
                float n0v = tanhf(accG[3][n8][c0 + 0] + gxc.x);
                float n1v = tanhf(accG[3][n8][c0 + 1] + gxc.y);

                float cn0 = f0 * c10 + i0 * n0v;
                float cn1 = f1 * c11 + i1 * n1v;
                float hn0 = o0 * tanhf(cn0);
                float hn1 = o1 * tanhf(cn1);

                size_t off = (size_t)m * HH + j;
                *(float2*)&c_out[off] = make_float2(cn0, cn1);
                *(float2*)&h_out[off] = make_float2(hn0, hn1);
                *(__half2*)&chi_o[off] = __halves2half2(
                    __float2half_rn(cn0), __float2half_rn(cn1));
                *(__half2*)&hhi_o[off] = __halves2half2(
                    __float2half_rn(hn0), __float2half_rn(hn1));
            }
        }

        grid_bar(t);
    }
}

// ---------------------------------------------------------------------------
__global__ void head_kernel(const float* __restrict__ Wo, const float* __restrict__ bo,
                            const float* __restrict__ Ws, const float* __restrict__ bs,
                            float* __restrict__ out)
{
    __shared__ float hrow[HH];
    __shared__ float fc[FCC];
    const int b = blockIdx.x;
    const float* h = g_h[0] + (size_t)b * HH;
    for (int k = threadIdx.x; k < HH; k += blockDim.x) hrow[k] = h[k];
    __syncthreads();

    const int j = threadIdx.x;
    float s = bo[j];
    for (int k = 0; k < HH; k++) s += hrow[k] * Wo[(size_t)k * FCC + j];
    fc[j] = fmaxf(s, 0.0f);
    __syncthreads();

    if (j < OO) {
        float r = bs[j];
        for (int q = 0; q < FCC; q++) r += fc[q] * Ws[(size_t)q * OO + j];
        out[(size_t)b * OO + j] = r;
    }
}

// ---------------------------------------------------------------------------
extern "C" void kernel_launch(void* const* d_in, const int* in_sizes, int n_in,
                              void* d_out, int out_size)
{
    const float* x   = (const float*)d_in[0];
    const float* tmv = (const float*)d_in[1];
    const float* Wi  = (const float*)d_in[2];
    const float* Ui  = (const float*)d_in[3];
    const float* bi  = (const float*)d_in[4];
    const float* Wf  = (const float*)d_in[5];
    const float* Uf  = (const float*)d_in[6];
    const float* bf  = (const float*)d_in[7];
    const float* Wog = (const float*)d_in[8];
    const float* Uog = (const float*)d_in[9];
    const float* bog = (const float*)d_in[10];
    const float* Wc  = (const float*)d_in[11];
    const float* Uc  = (const float*)d_in[12];
    const float* bc  = (const float*)d_in[13];
    const float* Wd  = (const float*)d_in[14];
    const float* bd  = (const float*)d_in[15];
    const float* Wo  = (const float*)d_in[16];
    const float* bo  = (const float*)d_in[17];
    const float* Ws  = (const float*)d_in[18];
    const float* bs  = (const float*)d_in[19];
    float* out = (float*)d_out;

    static bool attr_done = false;
    if (!attr_done) {
        cudaFuncSetAttribute(tlstm_scan,
                             cudaFuncAttributeMaxDynamicSharedMemorySize,
                             SCAN_SMEM_BYTES);
        attr_done = true;
    }

    init_state<<<(BB * HH + 255) / 256, 256>>>();

    {   size_t n = (size_t)SS * BB * DD;
        convert_x<<<(unsigned)((n + 255) / 256), 256>>>(x); }
    {   size_t n = (size_t)KP * G4;
        prep_wstack<<<(unsigned)((n + 255) / 256), 256>>>(Wi, Wf, Wog, Wc); }
    {   size_t n = (size_t)KP * N5;
        prep_ustack<<<(unsigned)((n + 255) / 256), 256>>>(Ui, Uf, Uog, Uc, Wd); }
    prep_bias<<<(G4 + 255) / 256, 256>>>(bi, bf, bog, bc);

    dim3 gg(16, 1024);      // x = n-blocks fast -> B L2-resident
    gemm_pre<<<gg, 256>>>();

    dim3 gs(8, 16);
    tlstm_scan<<<gs, 256, SCAN_SMEM_BYTES>>>(tmv, bd);

    head_kernel<<<BB, FCC>>>(Wo, bo, Ws, bs, out);
}